// round 3
// baseline (speedup 1.0000x reference)
#include <cuda_runtime.h>
#include <cuda_bf16.h>
#include <cstddef>

#define Bq   128
#define Tq   64
#define Hq   512
#define Vq   10000
#define Gq   2048            // 4*H
#define BTq  (Bq*Tq)         // 8192
#define NBLK 79              // ceil(V/128)
#define PNB  128             // persistent grid blocks
#define PNT  128             // persistent block threads

// ---------------- scratch (__device__ globals; no allocation allowed) ----------------
__device__ float g_xw0[(size_t)BTq * Gq];      // 67 MB : x @ W0x + b0 for all (b,t)
__device__ float g_out[(size_t)BTq * Hq];      // 16 MB : LSTM layer-1 outputs
__device__ float g_pm[(size_t)BTq * NBLK];     // per-(row, colblock) partial max
__device__ float g_ps[(size_t)BTq * NBLK];     // per-(row, colblock) partial sumexp
__device__ float g_zl[BTq];                    // logit at label
__device__ float g_xent[BTq];
// transposed state [j][b] for coalesced, transpose-free GEMM tile loads
__device__ float g_h0T[2][Hq * Bq];
__device__ float g_h1T[2][Hq * Bq];
__device__ float g_o0T[Hq * Bq];
__device__ unsigned g_barcnt;
__device__ unsigned g_barsense;

__device__ __forceinline__ float sigf(float x) { return 1.f / (1.f + expf(-x)); }

// ---------------- grid barrier (all PNB blocks co-resident) ----------------
__device__ __forceinline__ void grid_barrier(unsigned& sense) {
    __syncthreads();
    if (threadIdx.x == 0) {
        sense ^= 1u;
        __threadfence();
        unsigned a = atomicAdd(&g_barcnt, 1u);
        if (a == PNB - 1) {
            g_barcnt = 0;
            __threadfence();
            *(volatile unsigned*)&g_barsense = sense;
        } else {
            while (*(volatile unsigned*)&g_barsense != sense) __nanosleep(40);
        }
        __threadfence();
    }
    __syncthreads();
}

// ---------------- 128x128x16 SGEMM with store epilogue (xw0) ----------------
__global__ void k_xw0(const float* __restrict__ emb, const int* __restrict__ feat,
                      const float* __restrict__ Bm, const float* __restrict__ bias) {
    const int N = Gq, K = Hq;
    __shared__ float As[16][128];
    __shared__ float Bs[16][128];
    const int tid = threadIdx.x;           // 256 threads
    const int bx = blockIdx.x, by = blockIdx.y;
    const int tx = tid & 15, ty = tid >> 4;

    float acc[8][8];
#pragma unroll
    for (int i = 0; i < 8; ++i)
#pragma unroll
        for (int j = 0; j < 8; ++j) acc[i][j] = 0.f;

    for (int k0 = 0; k0 < K; k0 += 16) {
#pragma unroll
        for (int it = 0; it < 2; ++it) {
            int item = tid * 2 + it;       // 0..511
            int row  = item >> 2;
            int q    = item & 3;
            int gm   = by * 128 + row;
            const float* ap = emb + (size_t)feat[gm] * K;
            float4 v = *(const float4*)(ap + k0 + q * 4);
            As[q*4+0][row] = v.x; As[q*4+1][row] = v.y;
            As[q*4+2][row] = v.z; As[q*4+3][row] = v.w;
        }
#pragma unroll
        for (int it = 0; it < 2; ++it) {
            int item = tid * 2 + it;
            int kr = item >> 5;
            int qc = item & 31;
            int gn = bx * 128 + qc * 4;
            float4 v = *(const float4*)(Bm + (size_t)(k0 + kr) * N + gn);
            *(float4*)&Bs[kr][qc * 4] = v;
        }
        __syncthreads();
#pragma unroll
        for (int k = 0; k < 16; ++k) {
            float a[8], b[8];
#pragma unroll
            for (int i = 0; i < 8; ++i) a[i] = As[k][ty * 8 + i];
#pragma unroll
            for (int j = 0; j < 8; ++j) b[j] = Bs[k][tx * 8 + j];
#pragma unroll
            for (int i = 0; i < 8; ++i)
#pragma unroll
                for (int j = 0; j < 8; ++j) acc[i][j] = fmaf(a[i], b[j], acc[i][j]);
        }
        __syncthreads();
    }
#pragma unroll
    for (int i = 0; i < 8; ++i) {
        int gm = by * 128 + ty * 8 + i;
        float* crow = g_xw0 + (size_t)gm * N;
#pragma unroll
        for (int j = 0; j < 8; ++j) {
            int gn = bx * 128 + tx * 8 + j;
            crow[gn] = acc[i][j] + bias[gn];
        }
    }
}

// ---------------- persistent 2-layer LSTM recurrence ----------------
// 128 blocks x 128 threads; block bx owns j in [bx*4, bx*4+4); warp jj = one j.
// lane owns rows lane*4..lane*4+3; c-state lives in registers for all 64 steps.
__global__ void __launch_bounds__(PNT, 1) lstm_persist(
        const int* __restrict__ seq_len,
        const float* __restrict__ W0h,
        const float* __restrict__ W1x,
        const float* __restrict__ W1h,
        const float* __restrict__ b1) {
    __shared__ float sa[32][128];   // k-chunk x rows (16 KB)
    __shared__ float sw[32][16];    // k-chunk x 16 gate cols (4 g x 4 j)
    const int tid  = threadIdx.x;
    const int jj   = tid >> 5;             // warp id: local j 0..3
    const int lane = tid & 31;             // row group: rows lane*4..+3
    const int j    = blockIdx.x * 4 + jj;  // global j
    unsigned sense = 0;

    int sl[4];
    float c0r[4], c1r[4];
#pragma unroll
    for (int rr = 0; rr < 4; ++rr) {
        sl[rr] = seq_len[lane * 4 + rr];
        c0r[rr] = 0.f; c1r[rr] = 0.f;
    }
    // zero-init h state for this block's j slice (t=0 reads buffer 0)
    for (int r = tid; r < 128; r += PNT) {
        for (int jl = 0; jl < 4; ++jl) {
            int jg = blockIdx.x * 4 + jl;
            g_h0T[0][jg * Bq + r] = 0.f;
            g_h1T[0][jg * Bq + r] = 0.f;
        }
    }
    grid_barrier(sense);

    for (int t = 0; t < Tq; ++t) {
        const int rb = t & 1, wb = rb ^ 1;

        // ===== layer 0: gates = h0 @ W0h[:, block cols]  (K = 512) =====
        {
            const float* __restrict__ hb = g_h0T[rb];
            float acc[4][4];
#pragma unroll
            for (int rr = 0; rr < 4; ++rr)
#pragma unroll
                for (int g = 0; g < 4; ++g) acc[rr][g] = 0.f;

            for (int k0 = 0; k0 < Hq; k0 += 32) {
                for (int it = tid; it < 1024; it += PNT) {   // 32k x 128r / 4
                    int kk = it >> 5, rq = it & 31;
                    *(float4*)&sa[kk][rq * 4] =
                        *(const float4*)(hb + (k0 + kk) * Bq + rq * 4);
                }
                for (int it = tid; it < 512; it += PNT) {    // 32k x 16c
                    int kk = it >> 4, col = it & 15;
                    int g = col >> 2, jl = col & 3;
                    sw[kk][col] = W0h[(size_t)(k0 + kk) * Gq + g * Hq + blockIdx.x * 4 + jl];
                }
                __syncthreads();
#pragma unroll
                for (int kk = 0; kk < 32; ++kk) {
                    float w0 = sw[kk][0 + jj], w1 = sw[kk][4 + jj];
                    float w2 = sw[kk][8 + jj], w3 = sw[kk][12 + jj];
                    float4 a4 = *(const float4*)&sa[kk][lane * 4];
                    float a[4] = {a4.x, a4.y, a4.z, a4.w};
#pragma unroll
                    for (int rr = 0; rr < 4; ++rr) {
                        acc[rr][0] = fmaf(a[rr], w0, acc[rr][0]);
                        acc[rr][1] = fmaf(a[rr], w1, acc[rr][1]);
                        acc[rr][2] = fmaf(a[rr], w2, acc[rr][2]);
                        acc[rr][3] = fmaf(a[rr], w3, acc[rr][3]);
                    }
                }
                __syncthreads();
            }
#pragma unroll
            for (int rr = 0; rr < 4; ++rr) {
                int b_ = lane * 4 + rr;
                size_t base = ((size_t)b_ * Tq + t) * Gq;
                float gi = acc[rr][0] + g_xw0[base + j];
                float gc_= acc[rr][1] + g_xw0[base + Hq + j];
                float gf = acc[rr][2] + g_xw0[base + 2*Hq + j];
                float go = acc[rr][3] + g_xw0[base + 3*Hq + j];
                bool m = t < sl[rr];
                float h_old = hb[j * Bq + b_];
                float cn = sigf(gf) * c0r[rr] + sigf(gi) * tanhf(gc_);
                float hn = sigf(go) * tanhf(cn);
                c0r[rr] = m ? cn : c0r[rr];
                float hw = m ? hn : h_old;
                g_h0T[wb][j * Bq + b_] = hw;
                g_o0T[j * Bq + b_]     = m ? hn : 0.f;
            }
        }
        grid_barrier(sense);   // o0T + h0T[wb] visible

        // ===== layer 1: gates = o0 @ W1x + h1 @ W1h  (K = 512 + 512) =====
        {
            const float* __restrict__ h1b = g_h1T[rb];
            float acc[4][4];
#pragma unroll
            for (int rr = 0; rr < 4; ++rr)
#pragma unroll
                for (int g = 0; g < 4; ++g) acc[rr][g] = 0.f;

#pragma unroll 1
            for (int ph = 0; ph < 2; ++ph) {
                const float* __restrict__ Ap = ph ? h1b : g_o0T;
                const float* __restrict__ Wp = ph ? W1h : W1x;
                for (int k0 = 0; k0 < Hq; k0 += 32) {
                    for (int it = tid; it < 1024; it += PNT) {
                        int kk = it >> 5, rq = it & 31;
                        *(float4*)&sa[kk][rq * 4] =
                            *(const float4*)(Ap + (k0 + kk) * Bq + rq * 4);
                    }
                    for (int it = tid; it < 512; it += PNT) {
                        int kk = it >> 4, col = it & 15;
                        int g = col >> 2, jl = col & 3;
                        sw[kk][col] = Wp[(size_t)(k0 + kk) * Gq + g * Hq + blockIdx.x * 4 + jl];
                    }
                    __syncthreads();
#pragma unroll
                    for (int kk = 0; kk < 32; ++kk) {
                        float w0 = sw[kk][0 + jj], w1 = sw[kk][4 + jj];
                        float w2 = sw[kk][8 + jj], w3 = sw[kk][12 + jj];
                        float4 a4 = *(const float4*)&sa[kk][lane * 4];
                        float a[4] = {a4.x, a4.y, a4.z, a4.w};
#pragma unroll
                        for (int rr = 0; rr < 4; ++rr) {
                            acc[rr][0] = fmaf(a[rr], w0, acc[rr][0]);
                            acc[rr][1] = fmaf(a[rr], w1, acc[rr][1]);
                            acc[rr][2] = fmaf(a[rr], w2, acc[rr][2]);
                            acc[rr][3] = fmaf(a[rr], w3, acc[rr][3]);
                        }
                    }
                    __syncthreads();
                }
            }
#pragma unroll
            for (int rr = 0; rr < 4; ++rr) {
                int b_ = lane * 4 + rr;
                float gi = acc[rr][0] + b1[j];
                float gc_= acc[rr][1] + b1[Hq + j];
                float gf = acc[rr][2] + b1[2*Hq + j];
                float go = acc[rr][3] + b1[3*Hq + j];
                bool m = t < sl[rr];
                float h_old = h1b[j * Bq + b_];
                float cn = sigf(gf) * c1r[rr] + sigf(gi) * tanhf(gc_);
                float hn = sigf(go) * tanhf(cn);
                c1r[rr] = m ? cn : c1r[rr];
                g_h1T[wb][j * Bq + b_] = m ? hn : h_old;
                g_out[((size_t)b_ * Tq + t) * Hq + j] = m ? hn : 0.f;
            }
        }
        grid_barrier(sense);   // protect o0T/h state before next step overwrites
    }
}

// ---------------- logits GEMM with fused softmax-stat epilogue ----------------
__global__ void k_logits_fused(const float* __restrict__ Bm,
                               const float* __restrict__ bias,
                               const int* __restrict__ labels) {
    const int N = Vq, K = Hq;
    __shared__ float As[16][128];
    __shared__ float Bs[16][128];
    __shared__ float pm[128][17];
    __shared__ float ps[128][17];
    const int tid = threadIdx.x;           // 256 threads
    const int bx = blockIdx.x, by = blockIdx.y;
    const int tx = tid & 15, ty = tid >> 4;

    float acc[8][8];
#pragma unroll
    for (int i = 0; i < 8; ++i)
#pragma unroll
        for (int j = 0; j < 8; ++j) acc[i][j] = 0.f;

    for (int k0 = 0; k0 < K; k0 += 16) {
#pragma unroll
        for (int it = 0; it < 2; ++it) {
            int item = tid * 2 + it;
            int row  = item >> 2;
            int q    = item & 3;
            int gm   = by * 128 + row;
            const float* ap = g_out + (size_t)gm * K;
            float4 v = *(const float4*)(ap + k0 + q * 4);
            As[q*4+0][row] = v.x; As[q*4+1][row] = v.y;
            As[q*4+2][row] = v.z; As[q*4+3][row] = v.w;
        }
#pragma unroll
        for (int it = 0; it < 2; ++it) {
            int item = tid * 2 + it;
            int kr = item >> 5;
            int qc = item & 31;
            int gn = bx * 128 + qc * 4;
            float4 v;
            if (gn + 3 < N) {
                v = *(const float4*)(Bm + (size_t)(k0 + kr) * N + gn);
            } else {
                v.x = (gn + 0 < N) ? Bm[(size_t)(k0+kr)*N + gn + 0] : 0.f;
                v.y = (gn + 1 < N) ? Bm[(size_t)(k0+kr)*N + gn + 1] : 0.f;
                v.z = (gn + 2 < N) ? Bm[(size_t)(k0+kr)*N + gn + 2] : 0.f;
                v.w = (gn + 3 < N) ? Bm[(size_t)(k0+kr)*N + gn + 3] : 0.f;
            }
            *(float4*)&Bs[kr][qc * 4] = v;
        }
        __syncthreads();
#pragma unroll
        for (int k = 0; k < 16; ++k) {
            float a[8], b[8];
#pragma unroll
            for (int i = 0; i < 8; ++i) a[i] = As[k][ty * 8 + i];
#pragma unroll
            for (int j = 0; j < 8; ++j) b[j] = Bs[k][tx * 8 + j];
#pragma unroll
            for (int i = 0; i < 8; ++i)
#pragma unroll
                for (int j = 0; j < 8; ++j) acc[i][j] = fmaf(a[i], b[j], acc[i][j]);
        }
        __syncthreads();
    }

    // epilogue: bias add, label capture, per-thread (max, sumexp) over 8 cols
#pragma unroll
    for (int i = 0; i < 8; ++i) {
        int gm  = by * 128 + ty * 8 + i;
        int lab = labels[gm];
        float v[8];
        float lm = -1e30f;
#pragma unroll
        for (int j = 0; j < 8; ++j) {
            int gn = bx * 128 + tx * 8 + j;
            if (gn < N) {
                v[j] = acc[i][j] + bias[gn];
                if (gn == lab) g_zl[gm] = v[j];
                lm = fmaxf(lm, v[j]);
            } else v[j] = -1e30f;
        }
        float lsum = 0.f;
#pragma unroll
        for (int j = 0; j < 8; ++j) lsum += expf(v[j] - lm);
        if (lm <= -1e30f) lsum = 0.f;   // fully out-of-range thread
        pm[ty * 8 + i][tx] = lm;
        ps[ty * 8 + i][tx] = lsum;
    }
    __syncthreads();
    if (tid < 128) {
        float m = -1e30f, s = 0.f;
#pragma unroll
        for (int x = 0; x < 16; ++x) {
            float m2 = pm[tid][x], s2 = ps[tid][x];
            float M = fmaxf(m, m2);
            s = s * expf(m - M) + s2 * expf(m2 - M);
            m = M;
        }
        int gm = by * 128 + tid;
        g_pm[(size_t)gm * NBLK + bx] = m;
        g_ps[(size_t)gm * NBLK + bx] = s;
    }
}

// ---------------- per-row merge of partial softmax stats; xent ----------------
__global__ void k_xent_reduce() {
    const int row  = blockIdx.x * 8 + (threadIdx.x >> 5);
    const int lane = threadIdx.x & 31;
    float m = -1e30f, s = 0.f;
    for (int p = lane; p < NBLK; p += 32) {
        float m2 = g_pm[(size_t)row * NBLK + p];
        float s2 = g_ps[(size_t)row * NBLK + p];
        float M = fmaxf(m, m2);
        s = s * expf(m - M) + s2 * expf(m2 - M);
        m = M;
    }
#pragma unroll
    for (int o = 16; o > 0; o >>= 1) {
        float m2 = __shfl_xor_sync(0xffffffff, m, o);
        float s2 = __shfl_xor_sync(0xffffffff, s, o);
        float M = fmaxf(m, m2);
        s = s * expf(m - M) + s2 * expf(m2 - M);
        m = M;
    }
    if (lane == 0) g_xent[row] = -(g_zl[row] - m - logf(s));
}

// ---------------- final masked reduction to scalar ----------------
__global__ void k_loss(const float* __restrict__ seq_mask, float* __restrict__ out) {
    const int t = threadIdx.x;    // 64 threads, one per timestep
    float sx = 0.f, sw_ = 0.f;
    for (int b = 0; b < Bq; ++b) {
        int i = b * Tq + t;
        float w = seq_mask[i];
        sx  += g_xent[i] * w;
        sw_ += w;
    }
    __shared__ float sh[64];
    sh[t] = sx / (sw_ + 1e-12f);
    __syncthreads();
    for (int o = 32; o > 0; o >>= 1) { if (t < o) sh[t] += sh[t + o]; __syncthreads(); }
    if (t == 0) out[0] = sh[0] / Tq;
}

// ---------------- launch ----------------
extern "C" void kernel_launch(void* const* d_in, const int* in_sizes, int n_in,
                              void* d_out, int out_size) {
    const int*   features = (const int*)  d_in[0];
    const int*   labels   = (const int*)  d_in[1];
    const int*   seq_len  = (const int*)  d_in[2];
    const float* seq_mask = (const float*)d_in[3];
    const float* emb      = (const float*)d_in[4];
    const float* W0x      = (const float*)d_in[5];
    const float* W0h      = (const float*)d_in[6];
    const float* b0       = (const float*)d_in[7];
    const float* W1x      = (const float*)d_in[8];
    const float* W1h      = (const float*)d_in[9];
    const float* b1       = (const float*)d_in[10];
    const float* smw      = (const float*)d_in[11];
    const float* smb      = (const float*)d_in[12];
    float* out = (float*)d_out;

    // x @ W0x + b0 for all timesteps (embedding gathered in A-tile loads)
    k_xw0<<<dim3(Gq / 128, BTq / 128), 256>>>(emb, features, W0x, b0);

    // whole 64-step 2-layer recurrence in one persistent kernel
    lstm_persist<<<PNB, PNT>>>(seq_len, W0h, W1x, W1h, b1);

    k_logits_fused<<<dim3(NBLK, BTq / 128), 256>>>(smw, smb, labels);
    k_xent_reduce<<<BTq / 8, 256>>>();
    k_loss<<<1, 64>>>(seq_mask, out);
}

// round 4
// speedup vs baseline: 1.4281x; 1.4281x over previous
#include <cuda_runtime.h>
#include <cuda_bf16.h>
#include <cstddef>
#include <cstdint>

#define Bq   128
#define Tq   64
#define Hq   512
#define Vq   10000
#define Gq   2048            // 4*H
#define BTq  (Bq*Tq)         // 8192
#define NBLK 79              // ceil(V/128)

// ---------------- scratch (__device__ globals; no allocation allowed) ----------------
__device__ float g_xw0[(size_t)BTq * Gq];      // 67 MB : x @ W0x + b0 for all (b,t)
__device__ float g_out[(size_t)BTq * Hq];      // 16 MB : LSTM layer-1 outputs
__device__ float g_pm[(size_t)BTq * NBLK];     // per-(row, colblock) partial max
__device__ float g_ps[(size_t)BTq * NBLK];     // per-(row, colblock) partial sumexp
__device__ float g_zl[BTq];                    // logit at label
__device__ float g_xent[BTq];
__device__ float g_h0[2][Bq * Hq];
__device__ float g_h1[2][Bq * Hq];
__device__ float g_c0[Bq * Hq];
__device__ float g_c1[Bq * Hq];
__device__ float g_o0[Bq * Hq];

__device__ __forceinline__ float sigf(float x) { return 1.f / (1.f + expf(-x)); }

__device__ __forceinline__ unsigned f2tf(float f) {
    unsigned u;
    asm("cvt.rna.tf32.f32 %0, %1;" : "=r"(u) : "f"(f));
    return u;
}

__device__ __forceinline__ void mma_tf32(float& d0, float& d1, float& d2, float& d3,
                                         unsigned a0, unsigned a1, unsigned a2, unsigned a3,
                                         unsigned b0, unsigned b1) {
    asm volatile(
        "mma.sync.aligned.m16n8k8.row.col.f32.tf32.tf32.f32 "
        "{%0,%1,%2,%3}, {%4,%5,%6,%7}, {%8,%9}, {%0,%1,%2,%3};"
        : "+f"(d0), "+f"(d1), "+f"(d2), "+f"(d3)
        : "r"(a0), "r"(a1), "r"(a2), "r"(a3), "r"(b0), "r"(b1));
}

// ---------------- init: zero initial states ----------------
__global__ void k_init() {
    int i = blockIdx.x * blockDim.x + threadIdx.x;
    if (i < Bq * Hq) {
        g_h0[0][i] = 0.f; g_c0[i] = 0.f;
        g_h1[0][i] = 0.f; g_c1[i] = 0.f;
    }
}

// =======================================================================
// tf32 tensor-core GEMM core: block tile 128x128, warp tile 32x64,
// k-chunk 32 (4 x m16n8k8).  As stride 36, Bs stride 136: conflict-free.
// =======================================================================
#define ASTR 36
#define BSTR 136

// ---------------- xw0 = gather(emb) @ W0x + b0  (N=2048, K=512) ----------------
__global__ void k_xw0_tf32(const float* __restrict__ emb, const int* __restrict__ feat,
                           const float* __restrict__ Bm, const float* __restrict__ bias) {
    const int N = Gq, K = Hq;
    __shared__ unsigned As[128 * ASTR];
    __shared__ unsigned Bs[32 * BSTR];
    const int tid = threadIdx.x;                 // 256
    const int bx = blockIdx.x, by = blockIdx.y;
    const int warp = tid >> 5, lane = tid & 31;
    const int wm = warp & 3, wn = warp >> 2;     // 4 x 2 warps
    const int gID = lane >> 2, tig = lane & 3;

    float acc[2][8][4];
#pragma unroll
    for (int mt = 0; mt < 2; ++mt)
#pragma unroll
        for (int nt = 0; nt < 8; ++nt)
#pragma unroll
            for (int e = 0; e < 4; ++e) acc[mt][nt][e] = 0.f;

    for (int k0 = 0; k0 < K; k0 += 32) {
        for (int it = tid; it < 1024; it += 256) {        // A: 128r x 32k
            int row = it >> 3, q = it & 7;
            const float* ap = emb + (size_t)feat[by * 128 + row] * K;
            float4 v = *(const float4*)(ap + k0 + q * 4);
            uint4 u = {f2tf(v.x), f2tf(v.y), f2tf(v.z), f2tf(v.w)};
            *(uint4*)&As[row * ASTR + q * 4] = u;
        }
        for (int it = tid; it < 1024; it += 256) {        // B: 32k x 128n
            int k = it >> 5, q = it & 31;
            int gn = bx * 128 + q * 4;
            float4 v = *(const float4*)(Bm + (size_t)(k0 + k) * N + gn);
            uint4 u = {f2tf(v.x), f2tf(v.y), f2tf(v.z), f2tf(v.w)};
            *(uint4*)&Bs[k * BSTR + q * 4] = u;
        }
        __syncthreads();
#pragma unroll
        for (int ks = 0; ks < 4; ++ks) {
            unsigned a[2][4];
#pragma unroll
            for (int mt = 0; mt < 2; ++mt) {
                int mr = wm * 32 + mt * 16;
                a[mt][0] = As[(mr + gID    ) * ASTR + ks * 8 + tig];
                a[mt][1] = As[(mr + gID + 8) * ASTR + ks * 8 + tig];
                a[mt][2] = As[(mr + gID    ) * ASTR + ks * 8 + tig + 4];
                a[mt][3] = As[(mr + gID + 8) * ASTR + ks * 8 + tig + 4];
            }
#pragma unroll
            for (int nt = 0; nt < 8; ++nt) {
                int nc = wn * 64 + nt * 8 + gID;
                unsigned b0 = Bs[(ks * 8 + tig    ) * BSTR + nc];
                unsigned b1 = Bs[(ks * 8 + tig + 4) * BSTR + nc];
#pragma unroll
                for (int mt = 0; mt < 2; ++mt)
                    mma_tf32(acc[mt][nt][0], acc[mt][nt][1], acc[mt][nt][2], acc[mt][nt][3],
                             a[mt][0], a[mt][1], a[mt][2], a[mt][3], b0, b1);
            }
        }
        __syncthreads();
    }
    // epilogue: bias + store (float2: c0,c1 are adjacent columns)
#pragma unroll
    for (int mt = 0; mt < 2; ++mt) {
#pragma unroll
        for (int er = 0; er < 2; ++er) {
            int gm = by * 128 + wm * 32 + mt * 16 + gID + er * 8;
            float* crow = g_xw0 + (size_t)gm * N;
#pragma unroll
            for (int nt = 0; nt < 8; ++nt) {
                int gn = bx * 128 + wn * 64 + nt * 8 + tig * 2;
                float2 v = {acc[mt][nt][er * 2 + 0] + bias[gn],
                            acc[mt][nt][er * 2 + 1] + bias[gn + 1]};
                *(float2*)(crow + gn) = v;
            }
        }
    }
}

// ---------------- logits = g_out @ softmax_w + b, fused softmax stats ----------------
__global__ void k_logits_tf32(const float* __restrict__ Bm,
                              const float* __restrict__ bias,
                              const int* __restrict__ labels) {
    const int N = Vq, K = Hq;
    __shared__ unsigned As[128 * ASTR];
    __shared__ unsigned Bs[32 * BSTR];
    __shared__ float pm[128][9];
    __shared__ float ps[128][9];
    const int tid = threadIdx.x;                 // 256
    const int bx = blockIdx.x, by = blockIdx.y;
    const int warp = tid >> 5, lane = tid & 31;
    const int wm = warp & 3, wn = warp >> 2;
    const int gID = lane >> 2, tig = lane & 3;

    float acc[2][8][4];
#pragma unroll
    for (int mt = 0; mt < 2; ++mt)
#pragma unroll
        for (int nt = 0; nt < 8; ++nt)
#pragma unroll
            for (int e = 0; e < 4; ++e) acc[mt][nt][e] = 0.f;

    for (int k0 = 0; k0 < K; k0 += 32) {
        for (int it = tid; it < 1024; it += 256) {
            int row = it >> 3, q = it & 7;
            const float* ap = g_out + (size_t)(by * 128 + row) * K;
            float4 v = *(const float4*)(ap + k0 + q * 4);
            uint4 u = {f2tf(v.x), f2tf(v.y), f2tf(v.z), f2tf(v.w)};
            *(uint4*)&As[row * ASTR + q * 4] = u;
        }
        for (int it = tid; it < 1024; it += 256) {
            int k = it >> 5, q = it & 31;
            int gn = bx * 128 + q * 4;
            float4 v;
            const float* bp = Bm + (size_t)(k0 + k) * N;
            if (gn + 3 < N) v = *(const float4*)(bp + gn);
            else {
                v.x = (gn + 0 < N) ? bp[gn + 0] : 0.f;
                v.y = (gn + 1 < N) ? bp[gn + 1] : 0.f;
                v.z = (gn + 2 < N) ? bp[gn + 2] : 0.f;
                v.w = (gn + 3 < N) ? bp[gn + 3] : 0.f;
            }
            uint4 u = {f2tf(v.x), f2tf(v.y), f2tf(v.z), f2tf(v.w)};
            *(uint4*)&Bs[k * BSTR + q * 4] = u;
        }
        __syncthreads();
#pragma unroll
        for (int ks = 0; ks < 4; ++ks) {
            unsigned a[2][4];
#pragma unroll
            for (int mt = 0; mt < 2; ++mt) {
                int mr = wm * 32 + mt * 16;
                a[mt][0] = As[(mr + gID    ) * ASTR + ks * 8 + tig];
                a[mt][1] = As[(mr + gID + 8) * ASTR + ks * 8 + tig];
                a[mt][2] = As[(mr + gID    ) * ASTR + ks * 8 + tig + 4];
                a[mt][3] = As[(mr + gID + 8) * ASTR + ks * 8 + tig + 4];
            }
#pragma unroll
            for (int nt = 0; nt < 8; ++nt) {
                int nc = wn * 64 + nt * 8 + gID;
                unsigned b0 = Bs[(ks * 8 + tig    ) * BSTR + nc];
                unsigned b1 = Bs[(ks * 8 + tig + 4) * BSTR + nc];
#pragma unroll
                for (int mt = 0; mt < 2; ++mt)
                    mma_tf32(acc[mt][nt][0], acc[mt][nt][1], acc[mt][nt][2], acc[mt][nt][3],
                             a[mt][0], a[mt][1], a[mt][2], a[mt][3], b0, b1);
            }
        }
        __syncthreads();
    }

    // epilogue: per-thread 16 cols for each of its 4 rows -> block partials
#pragma unroll
    for (int mt = 0; mt < 2; ++mt) {
#pragma unroll
        for (int er = 0; er < 2; ++er) {
            int lr = wm * 32 + mt * 16 + gID + er * 8;
            int gm = by * 128 + lr;
            int lab = labels[gm];
            float lm = -1e30f, lsum = 0.f;
            float v[16];
#pragma unroll
            for (int nt = 0; nt < 8; ++nt) {
#pragma unroll
                for (int e = 0; e < 2; ++e) {
                    int gn = bx * 128 + wn * 64 + nt * 8 + tig * 2 + e;
                    float c = acc[mt][nt][er * 2 + e];
                    if (gn < N) {
                        float z = c + bias[gn];
                        v[nt * 2 + e] = z;
                        if (gn == lab) g_zl[gm] = z;
                        lm = fmaxf(lm, z);
                    } else v[nt * 2 + e] = -1e30f;
                }
            }
#pragma unroll
            for (int q = 0; q < 16; ++q) lsum += expf(v[q] - lm);
            if (lm <= -1e30f) lsum = 0.f;
            pm[lr][wn * 4 + tig] = lm;
            ps[lr][wn * 4 + tig] = lsum;
        }
    }
    __syncthreads();
    if (tid < 128) {
        float m = -1e30f, s = 0.f;
#pragma unroll
        for (int x = 0; x < 8; ++x) {
            float m2 = pm[tid][x], s2 = ps[tid][x];
            float M = fmaxf(m, m2);
            s = s * expf(m - M) + s2 * expf(m2 - M);
            m = M;
        }
        int gm = by * 128 + tid;
        g_pm[(size_t)gm * NBLK + bx] = m;
        g_ps[(size_t)gm * NBLK + bx] = s;
    }
}

// ---------------- LSTM step kernels (known-good R2 versions) ----------------
__global__ void lstm_step0(const int* __restrict__ seq_len,
                           const float* __restrict__ W0h, int t) {
    __shared__ float sa[32][32];
    __shared__ float sw[32][64];
    const int tid = threadIdx.x;
    const int j0 = (blockIdx.x & 31) * 16;
    const int r0 = (blockIdx.x >> 5) * 32;
    const int jj = tid & 15, rg = tid >> 4;
    const int rb = t & 1, wb = rb ^ 1;
    const float* hbuf = g_h0[rb];

    float acc[2][4] = {};
    for (int k0 = 0; k0 < Hq; k0 += 32) {
        for (int it = tid; it < 1024; it += 256) {
            int r = it >> 5, kk = it & 31;
            sa[kk][r] = hbuf[(r0 + r) * Hq + k0 + kk];
        }
        for (int it = tid; it < 2048; it += 256) {
            int kk = it >> 6, gc = it & 63;
            int g = gc >> 4, jl = gc & 15;
            sw[kk][gc] = W0h[(size_t)(k0 + kk) * Gq + g * Hq + j0 + jl];
        }
        __syncthreads();
#pragma unroll
        for (int kk = 0; kk < 32; ++kk) {
            float w0 = sw[kk][jj], w1 = sw[kk][16 + jj];
            float w2 = sw[kk][32 + jj], w3 = sw[kk][48 + jj];
#pragma unroll
            for (int rr = 0; rr < 2; ++rr) {
                float a = sa[kk][rg * 2 + rr];
                acc[rr][0] = fmaf(a, w0, acc[rr][0]);
                acc[rr][1] = fmaf(a, w1, acc[rr][1]);
                acc[rr][2] = fmaf(a, w2, acc[rr][2]);
                acc[rr][3] = fmaf(a, w3, acc[rr][3]);
            }
        }
        __syncthreads();
    }
#pragma unroll
    for (int rr = 0; rr < 2; ++rr) {
        int b_ = r0 + rg * 2 + rr;
        int j  = j0 + jj;
        size_t base = ((size_t)b_ * Tq + t) * Gq;
        float gi = acc[rr][0] + g_xw0[base + j];
        float gc_= acc[rr][1] + g_xw0[base + Hq + j];
        float gf = acc[rr][2] + g_xw0[base + 2*Hq + j];
        float go = acc[rr][3] + g_xw0[base + 3*Hq + j];
        bool m = t < seq_len[b_];
        int s = b_ * Hq + j;
        float c_old = g_c0[s], h_old = hbuf[s];
        float cn = sigf(gf) * c_old + sigf(gi) * tanhf(gc_);
        float hn = sigf(go) * tanhf(cn);
        g_c0[s]     = m ? cn : c_old;
        g_h0[wb][s] = m ? hn : h_old;
        g_o0[s]     = m ? hn : 0.f;
    }
}

__global__ void lstm_step1(const int* __restrict__ seq_len,
                           const float* __restrict__ W1x,
                           const float* __restrict__ W1h,
                           const float* __restrict__ b1, int t) {
    __shared__ float sa[32][32];
    __shared__ float sw[32][64];
    const int tid = threadIdx.x;
    const int j0 = (blockIdx.x & 31) * 16;
    const int r0 = (blockIdx.x >> 5) * 32;
    const int jj = tid & 15, rg = tid >> 4;
    const int rb = t & 1, wb = rb ^ 1;
    const float* h1buf = g_h1[rb];

    float acc[2][4] = {};
#pragma unroll 1
    for (int ph = 0; ph < 2; ++ph) {
        const float* Ap = ph ? h1buf : g_o0;
        const float* Wp = ph ? W1h : W1x;
        for (int k0 = 0; k0 < Hq; k0 += 32) {
            for (int it = tid; it < 1024; it += 256) {
                int r = it >> 5, kk = it & 31;
                sa[kk][r] = Ap[(r0 + r) * Hq + k0 + kk];
            }
            for (int it = tid; it < 2048; it += 256) {
                int kk = it >> 6, gc = it & 63;
                int g = gc >> 4, jl = gc & 15;
                sw[kk][gc] = Wp[(size_t)(k0 + kk) * Gq + g * Hq + j0 + jl];
            }
            __syncthreads();
#pragma unroll
            for (int kk = 0; kk < 32; ++kk) {
                float w0 = sw[kk][jj], w1 = sw[kk][16 + jj];
                float w2 = sw[kk][32 + jj], w3 = sw[kk][48 + jj];
#pragma unroll
                for (int rr = 0; rr < 2; ++rr) {
                    float a = sa[kk][rg * 2 + rr];
                    acc[rr][0] = fmaf(a, w0, acc[rr][0]);
                    acc[rr][1] = fmaf(a, w1, acc[rr][1]);
                    acc[rr][2] = fmaf(a, w2, acc[rr][2]);
                    acc[rr][3] = fmaf(a, w3, acc[rr][3]);
                }
            }
            __syncthreads();
        }
    }
#pragma unroll
    for (int rr = 0; rr < 2; ++rr) {
        int b_ = r0 + rg * 2 + rr;
        int j  = j0 + jj;
        float gi = acc[rr][0] + b1[j];
        float gc_= acc[rr][1] + b1[Hq + j];
        float gf = acc[rr][2] + b1[2*Hq + j];
        float go = acc[rr][3] + b1[3*Hq + j];
        bool m = t < seq_len[b_];
        int s = b_ * Hq + j;
        float c_old = g_c1[s], h_old = h1buf[s];
        float cn = sigf(gf) * c_old + sigf(gi) * tanhf(gc_);
        float hn = sigf(go) * tanhf(cn);
        g_c1[s]     = m ? cn : c_old;
        g_h1[wb][s] = m ? hn : h_old;
        g_out[((size_t)b_ * Tq + t) * Hq + j] = m ? hn : 0.f;
    }
}

// ---------------- per-row merge of partial softmax stats; xent ----------------
__global__ void k_xent_reduce() {
    const int row  = blockIdx.x * 8 + (threadIdx.x >> 5);
    const int lane = threadIdx.x & 31;
    float m = -1e30f, s = 0.f;
    for (int p = lane; p < NBLK; p += 32) {
        float m2 = g_pm[(size_t)row * NBLK + p];
        float s2 = g_ps[(size_t)row * NBLK + p];
        float M = fmaxf(m, m2);
        s = s * expf(m - M) + s2 * expf(m2 - M);
        m = M;
    }
#pragma unroll
    for (int o = 16; o > 0; o >>= 1) {
        float m2 = __shfl_xor_sync(0xffffffff, m, o);
        float s2 = __shfl_xor_sync(0xffffffff, s, o);
        float M = fmaxf(m, m2);
        s = s * expf(m - M) + s2 * expf(m2 - M);
        m = M;
    }
    if (lane == 0) g_xent[row] = -(g_zl[row] - m - logf(s));
}

// ---------------- final masked reduction to scalar ----------------
__global__ void k_loss(const float* __restrict__ seq_mask, float* __restrict__ out) {
    const int t = threadIdx.x;    // 64 threads, one per timestep
    float sx = 0.f, sw_ = 0.f;
    for (int b = 0; b < Bq; ++b) {
        int i = b * Tq + t;
        float w = seq_mask[i];
        sx  += g_xent[i] * w;
        sw_ += w;
    }
    __shared__ float sh[64];
    sh[t] = sx / (sw_ + 1e-12f);
    __syncthreads();
    for (int o = 32; o > 0; o >>= 1) { if (t < o) sh[t] += sh[t + o]; __syncthreads(); }
    if (t == 0) out[0] = sh[0] / Tq;
}

// ---------------- launch ----------------
extern "C" void kernel_launch(void* const* d_in, const int* in_sizes, int n_in,
                              void* d_out, int out_size) {
    const int*   features = (const int*)  d_in[0];
    const int*   labels   = (const int*)  d_in[1];
    const int*   seq_len  = (const int*)  d_in[2];
    const float* seq_mask = (const float*)d_in[3];
    const float* emb      = (const float*)d_in[4];
    const float* W0x      = (const float*)d_in[5];
    const float* W0h      = (const float*)d_in[6];
    const float* b0       = (const float*)d_in[7];
    const float* W1x      = (const float*)d_in[8];
    const float* W1h      = (const float*)d_in[9];
    const float* b1       = (const float*)d_in[10];
    const float* smw      = (const float*)d_in[11];
    const float* smb      = (const float*)d_in[12];
    float* out = (float*)d_out;

    k_init<<<(Bq * Hq + 255) / 256, 256>>>();

    // x @ W0x + b0 for all timesteps (tf32 tensor cores, embedding gathered)
    k_xw0_tf32<<<dim3(Gq / 128, BTq / 128), 256>>>(emb, features, W0x, b0);

    for (int t = 0; t < Tq; ++t) {
        lstm_step0<<<128, 256>>>(seq_len, W0h, t);
        lstm_step1<<<128, 256>>>(seq_len, W1x, W1h, b1, t);
    }

    k_logits_tf32<<<dim3(NBLK, BTq / 128), 256>>>(smw, smb, labels);
    k_xent_reduce<<<BTq / 8, 256>>>();
    k_loss<<<1, 64>>>(seq_mask, out);
}

// round 5
// speedup vs baseline: 3.6023x; 2.5225x over previous
#include <cuda_runtime.h>
#include <cuda_bf16.h>
#include <cstddef>
#include <cstdint>

#define Bq   128
#define Tq   64
#define Hq   512
#define Vq   10000
#define Gq   2048            // 4*H
#define BTq  (Bq*Tq)         // 8192
#define NBLK 79              // ceil(V/128)

// ---------------- scratch (__device__ globals; no allocation allowed) ----------------
__device__ float g_xw0[(size_t)BTq * Gq];      // 67 MB
__device__ float g_out[(size_t)BTq * Hq];      // 16 MB
__device__ float g_pm[(size_t)BTq * NBLK];
__device__ float g_ps[(size_t)BTq * NBLK];
__device__ float g_zl[BTq];
__device__ float g_xent[BTq];
__device__ float g_h0[2][Bq * Hq];
__device__ float g_h1[2][Bq * Hq];
__device__ float g_c0[Bq * Hq];
__device__ float g_c1[Bq * Hq];
__device__ float g_o0[Bq * Hq];

__device__ __forceinline__ float sigf(float x) { return 1.f / (1.f + expf(-x)); }

__device__ __forceinline__ uint32_t s2u(const void* p) {
    return (uint32_t)__cvta_generic_to_shared(p);
}
__device__ __forceinline__ void cpa16(uint32_t dst, const void* src) {
    asm volatile("cp.async.cg.shared.global [%0], [%1], 16;" :: "r"(dst), "l"(src));
}
__device__ __forceinline__ void cpa16p(uint32_t dst, const void* src, bool pred) {
    int sz = pred ? 16 : 0;
    asm volatile("cp.async.cg.shared.global [%0], [%1], 16, %2;" :: "r"(dst), "l"(src), "r"(sz));
}
#define CP_COMMIT asm volatile("cp.async.commit_group;")
#define CP_WAIT1  asm volatile("cp.async.wait_group 1;")

__device__ __forceinline__ void mma_tf32(float& d0, float& d1, float& d2, float& d3,
                                         unsigned a0, unsigned a1, unsigned a2, unsigned a3,
                                         unsigned b0, unsigned b1) {
    asm volatile(
        "mma.sync.aligned.m16n8k8.row.col.f32.tf32.tf32.f32 "
        "{%0,%1,%2,%3}, {%4,%5,%6,%7}, {%8,%9}, {%0,%1,%2,%3};"
        : "+f"(d0), "+f"(d1), "+f"(d2), "+f"(d3)
        : "r"(a0), "r"(a1), "r"(a2), "r"(a3), "r"(b0), "r"(b1));
}

// ---------------- init ----------------
__global__ void k_init() {
    int i = blockIdx.x * blockDim.x + threadIdx.x;
    if (i < Bq * Hq) {
        g_h0[0][i] = 0.f; g_c0[i] = 0.f;
        g_h1[0][i] = 0.f; g_c1[i] = 0.f;
    }
}

// =======================================================================
// tf32 GEMM: block 128x128, warp 32x64, k-chunk 16, 2-stage cp.async.
// As [row][k] stride 20, Bs [k][n] stride 136 — conflict-free fragments.
// =======================================================================
#define ASTR 20
#define BSTR 136

// ---------------- xw0 = gather(emb) @ W0x + b0  (N=2048, K=512) ----------------
__global__ void k_xw0_tf32(const float* __restrict__ emb, const int* __restrict__ feat,
                           const float* __restrict__ Bm, const float* __restrict__ bias) {
    const int N = Gq, K = Hq;
    __shared__ float As[2][128 * ASTR];
    __shared__ float Bs[2][16 * BSTR];
    const int tid = threadIdx.x;                 // 256
    const int bx = blockIdx.x, by = blockIdx.y;
    const int warp = tid >> 5, lane = tid & 31;
    const int wm = warp & 3, wn = warp >> 2;
    const int gID = lane >> 2, tig = lane & 3;

    // fill-role precompute
    const int arow = tid >> 2;                   // 0..63 (+64 for second)
    const int aq   = (tid & 3) * 4;
    const float* asrc0 = emb + (size_t)feat[by * 128 + arow] * K + aq;
    const float* asrc1 = emb + (size_t)feat[by * 128 + arow + 64] * K + aq;
    const int bk = tid >> 5, bq = tid & 31;      // k 0..7 (+8), n-quad
    const float* bsrc = Bm + (size_t)bk * N + bx * 128 + bq * 4;

    float acc[2][8][4];
#pragma unroll
    for (int mt = 0; mt < 2; ++mt)
#pragma unroll
        for (int nt = 0; nt < 8; ++nt)
#pragma unroll
            for (int e = 0; e < 4; ++e) acc[mt][nt][e] = 0.f;

    const int NC = K / 16;
    // prologue: stage 0
    {
        cpa16(s2u(&As[0][arow * ASTR + aq]), asrc0);
        cpa16(s2u(&As[0][(arow + 64) * ASTR + aq]), asrc1);
        cpa16(s2u(&Bs[0][bk * BSTR + bq * 4]), bsrc);
        cpa16(s2u(&Bs[0][(bk + 8) * BSTR + bq * 4]), bsrc + (size_t)8 * N);
    }
    CP_COMMIT;
    for (int c = 0; c < NC; ++c) {
        const int cur = c & 1, nxt = cur ^ 1;
        if (c + 1 < NC) {
            int k0 = (c + 1) * 16;
            cpa16(s2u(&As[nxt][arow * ASTR + aq]), asrc0 + k0);
            cpa16(s2u(&As[nxt][(arow + 64) * ASTR + aq]), asrc1 + k0);
            cpa16(s2u(&Bs[nxt][bk * BSTR + bq * 4]), bsrc + (size_t)k0 * N);
            cpa16(s2u(&Bs[nxt][(bk + 8) * BSTR + bq * 4]), bsrc + (size_t)(k0 + 8) * N);
        }
        CP_COMMIT;
        CP_WAIT1;
        __syncthreads();
        const unsigned* Au = (const unsigned*)As[cur];
        const unsigned* Bu = (const unsigned*)Bs[cur];
#pragma unroll
        for (int ks = 0; ks < 2; ++ks) {
            unsigned a[2][4];
#pragma unroll
            for (int mt = 0; mt < 2; ++mt) {
                int mr = wm * 32 + mt * 16;
                a[mt][0] = Au[(mr + gID    ) * ASTR + ks * 8 + tig];
                a[mt][1] = Au[(mr + gID + 8) * ASTR + ks * 8 + tig];
                a[mt][2] = Au[(mr + gID    ) * ASTR + ks * 8 + tig + 4];
                a[mt][3] = Au[(mr + gID + 8) * ASTR + ks * 8 + tig + 4];
            }
#pragma unroll
            for (int nt = 0; nt < 8; ++nt) {
                int nc = wn * 64 + nt * 8 + gID;
                unsigned b0 = Bu[(ks * 8 + tig    ) * BSTR + nc];
                unsigned b1 = Bu[(ks * 8 + tig + 4) * BSTR + nc];
#pragma unroll
                for (int mt = 0; mt < 2; ++mt)
                    mma_tf32(acc[mt][nt][0], acc[mt][nt][1], acc[mt][nt][2], acc[mt][nt][3],
                             a[mt][0], a[mt][1], a[mt][2], a[mt][3], b0, b1);
            }
        }
        __syncthreads();
    }
#pragma unroll
    for (int mt = 0; mt < 2; ++mt) {
#pragma unroll
        for (int er = 0; er < 2; ++er) {
            int gm = by * 128 + wm * 32 + mt * 16 + gID + er * 8;
            float* crow = g_xw0 + (size_t)gm * N;
#pragma unroll
            for (int nt = 0; nt < 8; ++nt) {
                int gn = bx * 128 + wn * 64 + nt * 8 + tig * 2;
                float2 v = {acc[mt][nt][er * 2 + 0] + bias[gn],
                            acc[mt][nt][er * 2 + 1] + bias[gn + 1]};
                *(float2*)(crow + gn) = v;
            }
        }
    }
}

// ---------------- logits GEMM + fused softmax stats ----------------
__global__ void k_logits_tf32(const float* __restrict__ Bm,
                              const float* __restrict__ bias,
                              const int* __restrict__ labels) {
    const int N = Vq, K = Hq;
    __shared__ float As[2][128 * ASTR];
    __shared__ float Bs[2][16 * BSTR];
    __shared__ float pm[128][9];
    __shared__ float ps[128][9];
    const int tid = threadIdx.x;
    const int bx = blockIdx.x, by = blockIdx.y;
    const int warp = tid >> 5, lane = tid & 31;
    const int wm = warp & 3, wn = warp >> 2;
    const int gID = lane >> 2, tig = lane & 3;

    const int arow = tid >> 2;
    const int aq   = (tid & 3) * 4;
    const float* asrc0 = g_out + (size_t)(by * 128 + arow) * K + aq;
    const float* asrc1 = asrc0 + (size_t)64 * K;
    const int bk = tid >> 5, bq = tid & 31;
    const int gnq = bx * 128 + bq * 4;
    const bool bpred = (gnq + 3 < N);            // N % 4 == 0
    const float* bsrc = Bm + (size_t)bk * N + (bpred ? gnq : 0);

    float acc[2][8][4];
#pragma unroll
    for (int mt = 0; mt < 2; ++mt)
#pragma unroll
        for (int nt = 0; nt < 8; ++nt)
#pragma unroll
            for (int e = 0; e < 4; ++e) acc[mt][nt][e] = 0.f;

    const int NC = K / 16;
    {
        cpa16(s2u(&As[0][arow * ASTR + aq]), asrc0);
        cpa16(s2u(&As[0][(arow + 64) * ASTR + aq]), asrc1);
        cpa16p(s2u(&Bs[0][bk * BSTR + bq * 4]), bsrc, bpred);
        cpa16p(s2u(&Bs[0][(bk + 8) * BSTR + bq * 4]), bsrc + (size_t)8 * N, bpred);
    }
    CP_COMMIT;
    for (int c = 0; c < NC; ++c) {
        const int cur = c & 1, nxt = cur ^ 1;
        if (c + 1 < NC) {
            int k0 = (c + 1) * 16;
            cpa16(s2u(&As[nxt][arow * ASTR + aq]), asrc0 + k0);
            cpa16(s2u(&As[nxt][(arow + 64) * ASTR + aq]), asrc1 + k0);
            cpa16p(s2u(&Bs[nxt][bk * BSTR + bq * 4]), bsrc + (size_t)k0 * N, bpred);
            cpa16p(s2u(&Bs[nxt][(bk + 8) * BSTR + bq * 4]), bsrc + (size_t)(k0 + 8) * N, bpred);
        }
        CP_COMMIT;
        CP_WAIT1;
        __syncthreads();
        const unsigned* Au = (const unsigned*)As[cur];
        const unsigned* Bu = (const unsigned*)Bs[cur];
#pragma unroll
        for (int ks = 0; ks < 2; ++ks) {
            unsigned a[2][4];
#pragma unroll
            for (int mt = 0; mt < 2; ++mt) {
                int mr = wm * 32 + mt * 16;
                a[mt][0] = Au[(mr + gID    ) * ASTR + ks * 8 + tig];
                a[mt][1] = Au[(mr + gID + 8) * ASTR + ks * 8 + tig];
                a[mt][2] = Au[(mr + gID    ) * ASTR + ks * 8 + tig + 4];
                a[mt][3] = Au[(mr + gID + 8) * ASTR + ks * 8 + tig + 4];
            }
#pragma unroll
            for (int nt = 0; nt < 8; ++nt) {
                int nc = wn * 64 + nt * 8 + gID;
                unsigned b0 = Bu[(ks * 8 + tig    ) * BSTR + nc];
                unsigned b1 = Bu[(ks * 8 + tig + 4) * BSTR + nc];
#pragma unroll
                for (int mt = 0; mt < 2; ++mt)
                    mma_tf32(acc[mt][nt][0], acc[mt][nt][1], acc[mt][nt][2], acc[mt][nt][3],
                             a[mt][0], a[mt][1], a[mt][2], a[mt][3], b0, b1);
            }
        }
        __syncthreads();
    }

#pragma unroll
    for (int mt = 0; mt < 2; ++mt) {
#pragma unroll
        for (int er = 0; er < 2; ++er) {
            int lr = wm * 32 + mt * 16 + gID + er * 8;
            int gm = by * 128 + lr;
            int lab = labels[gm];
            float lm = -1e30f, lsum = 0.f;
            float v[16];
#pragma unroll
            for (int nt = 0; nt < 8; ++nt) {
#pragma unroll
                for (int e = 0; e < 2; ++e) {
                    int gn = bx * 128 + wn * 64 + nt * 8 + tig * 2 + e;
                    float cc = acc[mt][nt][er * 2 + e];
                    if (gn < N) {
                        float z = cc + bias[gn];
                        v[nt * 2 + e] = z;
                        if (gn == lab) g_zl[gm] = z;
                        lm = fmaxf(lm, z);
                    } else v[nt * 2 + e] = -1e30f;
                }
            }
#pragma unroll
            for (int q = 0; q < 16; ++q) lsum += expf(v[q] - lm);
            if (lm <= -1e30f) lsum = 0.f;
            pm[lr][wn * 4 + tig] = lm;
            ps[lr][wn * 4 + tig] = lsum;
        }
    }
    __syncthreads();
    if (tid < 128) {
        float m = -1e30f, s = 0.f;
#pragma unroll
        for (int x = 0; x < 8; ++x) {
            float m2 = pm[tid][x], s2 = ps[tid][x];
            float M = fmaxf(m, m2);
            s = s * expf(m - M) + s2 * expf(m2 - M);
            m = M;
        }
        int gm = by * 128 + tid;
        g_pm[(size_t)gm * NBLK + bx] = m;
        g_ps[(size_t)gm * NBLK + bx] = s;
    }
}

// =======================================================================
// LSTM step kernels: epilogue operands prefetched at entry,
// cp.async 2-stage tile pipeline.  sa [r][k] str36, sw [k][gc].
// =======================================================================
__global__ void lstm_step0(const int* __restrict__ seq_len,
                           const float* __restrict__ W0h, int t) {
    __shared__ float sa[2][32][36];
    __shared__ float sw[2][32][64];
    const int tid = threadIdx.x;                 // 256
    const int j0 = (blockIdx.x & 31) * 16;
    const int r0 = (blockIdx.x >> 5) * 32;
    const int jj = tid & 15, rg = tid >> 4;
    const int rb = t & 1, wb = rb ^ 1;
    const float* __restrict__ hbuf = g_h0[rb];
    const int j = j0 + jj;

    // ---- epilogue prefetch (independent; stays in flight through GEMM) ----
    float xw[2][4], cold[2], hold[2];
    int sl[2];
#pragma unroll
    for (int rr = 0; rr < 2; ++rr) {
        int b_ = r0 + rg * 2 + rr;
        size_t base = ((size_t)b_ * Tq + t) * Gq;
#pragma unroll
        for (int g = 0; g < 4; ++g) xw[rr][g] = __ldg(&g_xw0[base + g * Hq + j]);
        cold[rr] = g_c0[b_ * Hq + j];
        hold[rr] = hbuf[b_ * Hq + j];
        sl[rr]   = __ldg(&seq_len[b_]);
    }

    // fill-role precompute: sa 256 cp (1/thr), sw 512 cp (2/thr)
    const int ar = tid >> 3, aq = (tid & 7) * 4;            // row, k-quad
    const float* asrc = hbuf + (size_t)(r0 + ar) * Hq + aq;
    const int wk0 = tid >> 4, wq = (tid & 15) * 4;          // k(+16), gc-quad
    const int wg = wq >> 4, wjl = wq & 15;
    const float* wsrc = W0h + (size_t)wk0 * Gq + wg * Hq + j0 + wjl;

    float acc[2][4] = {};
    {
        cpa16(s2u(&sa[0][ar][aq]), asrc);
        cpa16(s2u(&sw[0][wk0][wq]), wsrc);
        cpa16(s2u(&sw[0][wk0 + 16][wq]), wsrc + (size_t)16 * Gq);
    }
    CP_COMMIT;
    for (int c = 0; c < 16; ++c) {
        const int cur = c & 1, nxt = cur ^ 1;
        if (c + 1 < 16) {
            int k0 = (c + 1) * 32;
            cpa16(s2u(&sa[nxt][ar][aq]), asrc + k0);
            cpa16(s2u(&sw[nxt][wk0][wq]), wsrc + (size_t)k0 * Gq);
            cpa16(s2u(&sw[nxt][wk0 + 16][wq]), wsrc + (size_t)(k0 + 16) * Gq);
        }
        CP_COMMIT;
        CP_WAIT1;
        __syncthreads();
#pragma unroll
        for (int kk = 0; kk < 32; ++kk) {
            float w0 = sw[cur][kk][jj],      w1 = sw[cur][kk][16 + jj];
            float w2 = sw[cur][kk][32 + jj], w3 = sw[cur][kk][48 + jj];
#pragma unroll
            for (int rr = 0; rr < 2; ++rr) {
                float a = sa[cur][rg * 2 + rr][kk];
                acc[rr][0] = fmaf(a, w0, acc[rr][0]);
                acc[rr][1] = fmaf(a, w1, acc[rr][1]);
                acc[rr][2] = fmaf(a, w2, acc[rr][2]);
                acc[rr][3] = fmaf(a, w3, acc[rr][3]);
            }
        }
        __syncthreads();
    }
#pragma unroll
    for (int rr = 0; rr < 2; ++rr) {
        int b_ = r0 + rg * 2 + rr;
        float gi = acc[rr][0] + xw[rr][0];
        float gc_= acc[rr][1] + xw[rr][1];
        float gf = acc[rr][2] + xw[rr][2];
        float go = acc[rr][3] + xw[rr][3];
        bool m = t < sl[rr];
        int s = b_ * Hq + j;
        float cn = sigf(gf) * cold[rr] + sigf(gi) * tanhf(gc_);
        float hn = sigf(go) * tanhf(cn);
        g_c0[s]     = m ? cn : cold[rr];
        g_h0[wb][s] = m ? hn : hold[rr];
        g_o0[s]     = m ? hn : 0.f;
    }
}

__global__ void lstm_step1(const int* __restrict__ seq_len,
                           const float* __restrict__ W1x,
                           const float* __restrict__ W1h,
                           const float* __restrict__ b1, int t) {
    __shared__ float sa[2][32][36];
    __shared__ float sw[2][32][64];
    const int tid = threadIdx.x;
    const int j0 = (blockIdx.x & 31) * 16;
    const int r0 = (blockIdx.x >> 5) * 32;
    const int jj = tid & 15, rg = tid >> 4;
    const int rb = t & 1, wb = rb ^ 1;
    const float* __restrict__ h1buf = g_h1[rb];
    const int j = j0 + jj;

    float bb[4], cold[2], hold[2];
    int sl[2];
#pragma unroll
    for (int g = 0; g < 4; ++g) bb[g] = __ldg(&b1[g * Hq + j]);
#pragma unroll
    for (int rr = 0; rr < 2; ++rr) {
        int b_ = r0 + rg * 2 + rr;
        cold[rr] = g_c1[b_ * Hq + j];
        hold[rr] = h1buf[b_ * Hq + j];
        sl[rr]   = __ldg(&seq_len[b_]);
    }

    const int ar = tid >> 3, aq = (tid & 7) * 4;
    const int wk0 = tid >> 4, wq = (tid & 15) * 4;
    const int wg = wq >> 4, wjl = wq & 15;

    float acc[2][4] = {};
    // 32 chunks: cc<16 -> phase 0 (o0, W1x); cc>=16 -> phase 1 (h1, W1h)
    auto asrc_of = [&](int cc) -> const float* {
        const float* Ap = (cc < 16) ? g_o0 : h1buf;
        int k0 = (cc & 15) * 32;
        return Ap + (size_t)(r0 + ar) * Hq + k0 + aq;
    };
    auto wsrc_of = [&](int cc, int kofs) -> const float* {
        const float* Wp = (cc < 16) ? W1x : W1h;
        int k0 = (cc & 15) * 32;
        return Wp + (size_t)(k0 + wk0 + kofs) * Gq + wg * Hq + j0 + wjl;
    };
    {
        cpa16(s2u(&sa[0][ar][aq]), asrc_of(0));
        cpa16(s2u(&sw[0][wk0][wq]), wsrc_of(0, 0));
        cpa16(s2u(&sw[0][wk0 + 16][wq]), wsrc_of(0, 16));
    }
    CP_COMMIT;
    for (int cc = 0; cc < 32; ++cc) {
        const int cur = cc & 1, nxt = cur ^ 1;
        if (cc + 1 < 32) {
            cpa16(s2u(&sa[nxt][ar][aq]), asrc_of(cc + 1));
            cpa16(s2u(&sw[nxt][wk0][wq]), wsrc_of(cc + 1, 0));
            cpa16(s2u(&sw[nxt][wk0 + 16][wq]), wsrc_of(cc + 1, 16));
        }
        CP_COMMIT;
        CP_WAIT1;
        __syncthreads();
#pragma unroll
        for (int kk = 0; kk < 32; ++kk) {
            float w0 = sw[cur][kk][jj],      w1 = sw[cur][kk][16 + jj];
            float w2 = sw[cur][kk][32 + jj], w3 = sw[cur][kk][48 + jj];
#pragma unroll
            for (int rr = 0; rr < 2; ++rr) {
                float a = sa[cur][rg * 2 + rr][kk];
                acc[rr][0] = fmaf(a, w0, acc[rr][0]);
                acc[rr][1] = fmaf(a, w1, acc[rr][1]);
                acc[rr][2] = fmaf(a, w2, acc[rr][2]);
                acc[rr][3] = fmaf(a, w3, acc[rr][3]);
            }
        }
        __syncthreads();
    }
#pragma unroll
    for (int rr = 0; rr < 2; ++rr) {
        int b_ = r0 + rg * 2 + rr;
        float gi = acc[rr][0] + bb[0];
        float gc_= acc[rr][1] + bb[1];
        float gf = acc[rr][2] + bb[2];
        float go = acc[rr][3] + bb[3];
        bool m = t < sl[rr];
        int s = b_ * Hq + j;
        float cn = sigf(gf) * cold[rr] + sigf(gi) * tanhf(gc_);
        float hn = sigf(go) * tanhf(cn);
        g_c1[s]     = m ? cn : cold[rr];
        g_h1[wb][s] = m ? hn : hold[rr];
        g_out[((size_t)b_ * Tq + t) * Hq + j] = m ? hn : 0.f;
    }
}

// ---------------- partial softmax merge; xent ----------------
__global__ void k_xent_reduce() {
    const int row  = blockIdx.x * 8 + (threadIdx.x >> 5);
    const int lane = threadIdx.x & 31;
    float m = -1e30f, s = 0.f;
    for (int p = lane; p < NBLK; p += 32) {
        float m2 = g_pm[(size_t)row * NBLK + p];
        float s2 = g_ps[(size_t)row * NBLK + p];
        float M = fmaxf(m, m2);
        s = s * expf(m - M) + s2 * expf(m2 - M);
        m = M;
    }
#pragma unroll
    for (int o = 16; o > 0; o >>= 1) {
        float m2 = __shfl_xor_sync(0xffffffff, m, o);
        float s2 = __shfl_xor_sync(0xffffffff, s, o);
        float M = fmaxf(m, m2);
        s = s * expf(m - M) + s2 * expf(m2 - M);
        m = M;
    }
    if (lane == 0) g_xent[row] = -(g_zl[row] - m - logf(s));
}

// ---------------- final masked reduction ----------------
__global__ void k_loss(const float* __restrict__ seq_mask, float* __restrict__ out) {
    const int t = threadIdx.x;    // 64
    float sx = 0.f, sw_ = 0.f;
    for (int b = 0; b < Bq; ++b) {
        int i = b * Tq + t;
        float w = seq_mask[i];
        sx  += g_xent[i] * w;
        sw_ += w;
    }
    __shared__ float sh[64];
    sh[t] = sx / (sw_ + 1e-12f);
    __syncthreads();
    for (int o = 32; o > 0; o >>= 1) { if (t < o) sh[t] += sh[t + o]; __syncthreads(); }
    if (t == 0) out[0] = sh[0] / Tq;
}

// ---------------- launch ----------------
extern "C" void kernel_launch(void* const* d_in, const int* in_sizes, int n_in,
                              void* d_out, int out_size) {
    const int*   features = (const int*)  d_in[0];
    const int*   labels   = (const int*)  d_in[1];
    const int*   seq_len  = (const int*)  d_in[2];
    const float* seq_mask = (const float*)d_in[3];
    const float* emb      = (const float*)d_in[4];
    const float* W0x      = (const float*)d_in[5];
    const float* W0h      = (const float*)d_in[6];
    const float* b0       = (const float*)d_in[7];
    const float* W1x      = (const float*)d_in[8];
    const float* W1h      = (const float*)d_in[9];
    const float* b1       = (const float*)d_in[10];
    const float* smw      = (const float*)d_in[11];
    const float* smb      = (const float*)d_in[12];
    float* out = (float*)d_out;

    k_init<<<(Bq * Hq + 255) / 256, 256>>>();

    k_xw0_tf32<<<dim3(Gq / 128, BTq / 128), 256>>>(emb, features, W0x, b0);

    for (int t = 0; t < Tq; ++t) {
        lstm_step0<<<128, 256>>>(seq_len, W0h, t);
        lstm_step1<<<128, 256>>>(seq_len, W1x, W1h, b1, t);
    }

    k_logits_tf32<<<dim3(NBLK, BTq / 128), 256>>>(smw, smb, labels);
    k_xent_reduce<<<BTq / 8, 256>>>();
    k_loss<<<1, 64>>>(seq_mask, out);
}

// round 7
// speedup vs baseline: 3.8769x; 1.0762x over previous
#include <cuda_runtime.h>
#include <cuda_bf16.h>
#include <cstddef>
#include <cstdint>

#define Bq   128
#define Tq   64
#define Hq   512
#define Vq   10000
#define Gq   2048            // 4*H
#define BTq  (Bq*Tq)         // 8192
#define NBLK 79              // ceil(V/128)

// ---------------- scratch ----------------
__device__ float g_xw0[(size_t)BTq * Gq];
__device__ float g_out[(size_t)BTq * Hq];
__device__ float g_pm[(size_t)BTq * NBLK];
__device__ float g_ps[(size_t)BTq * NBLK];
__device__ float g_zl[BTq];
__device__ float g_xent[BTq];
__device__ float g_h0[2][Bq * Hq];
__device__ float g_h1[2][Bq * Hq];
__device__ float g_c0[Bq * Hq];
__device__ float g_c1[Bq * Hq];
__device__ float g_o0[Bq * Hq];

__device__ __forceinline__ float sigf(float x) { return 1.f / (1.f + expf(-x)); }

__device__ __forceinline__ uint32_t s2u(const void* p) {
    return (uint32_t)__cvta_generic_to_shared(p);
}
__device__ __forceinline__ void cpa16(uint32_t dst, const void* src) {
    asm volatile("cp.async.cg.shared.global [%0], [%1], 16;" :: "r"(dst), "l"(src));
}
__device__ __forceinline__ void cpa16p(uint32_t dst, const void* src, bool pred) {
    int sz = pred ? 16 : 0;
    asm volatile("cp.async.cg.shared.global [%0], [%1], 16, %2;" :: "r"(dst), "l"(src), "r"(sz));
}
#define CP_COMMIT asm volatile("cp.async.commit_group;")
#define CP_WAIT1  asm volatile("cp.async.wait_group 1;")

__device__ __forceinline__ void mma_tf32(float& d0, float& d1, float& d2, float& d3,
                                         unsigned a0, unsigned a1, unsigned a2, unsigned a3,
                                         unsigned b0, unsigned b1) {
    asm volatile(
        "mma.sync.aligned.m16n8k8.row.col.f32.tf32.tf32.f32 "
        "{%0,%1,%2,%3}, {%4,%5,%6,%7}, {%8,%9}, {%0,%1,%2,%3};"
        : "+f"(d0), "+f"(d1), "+f"(d2), "+f"(d3)
        : "r"(a0), "r"(a1), "r"(a2), "r"(a3), "r"(b0), "r"(b1));
}

// ---------------- init ----------------
__global__ void k_init() {
    int i = blockIdx.x * blockDim.x + threadIdx.x;
    if (i < Bq * Hq) {
        g_h0[0][i] = 0.f; g_c0[i] = 0.f;
        g_h1[0][i] = 0.f; g_c1[i] = 0.f;
    }
}

// =======================================================================
// big tf32 GEMMs: block 128x128, warp 32x64, k-chunk 16, 2-stage cp.async
// =======================================================================
#define ASTR 20
#define BSTR 136

__global__ void k_xw0_tf32(const float* __restrict__ emb, const int* __restrict__ feat,
                           const float* __restrict__ Bm, const float* __restrict__ bias) {
    const int N = Gq, K = Hq;
    __shared__ float As[2][128 * ASTR];
    __shared__ float Bs[2][16 * BSTR];
    const int tid = threadIdx.x;
    const int bx = blockIdx.x, by = blockIdx.y;
    const int warp = tid >> 5, lane = tid & 31;
    const int wm = warp & 3, wn = warp >> 2;
    const int gID = lane >> 2, tig = lane & 3;

    const int arow = tid >> 2;
    const int aq   = (tid & 3) * 4;
    const float* asrc0 = emb + (size_t)feat[by * 128 + arow] * K + aq;
    const float* asrc1 = emb + (size_t)feat[by * 128 + arow + 64] * K + aq;
    const int bk = tid >> 5, bq = tid & 31;
    const float* bsrc = Bm + (size_t)bk * N + bx * 128 + bq * 4;

    float acc[2][8][4];
#pragma unroll
    for (int mt = 0; mt < 2; ++mt)
#pragma unroll
        for (int nt = 0; nt < 8; ++nt)
#pragma unroll
            for (int e = 0; e < 4; ++e) acc[mt][nt][e] = 0.f;

    const int NC = K / 16;
    {
        cpa16(s2u(&As[0][arow * ASTR + aq]), asrc0);
        cpa16(s2u(&As[0][(arow + 64) * ASTR + aq]), asrc1);
        cpa16(s2u(&Bs[0][bk * BSTR + bq * 4]), bsrc);
        cpa16(s2u(&Bs[0][(bk + 8) * BSTR + bq * 4]), bsrc + (size_t)8 * N);
    }
    CP_COMMIT;
    for (int c = 0; c < NC; ++c) {
        const int cur = c & 1, nxt = cur ^ 1;
        if (c + 1 < NC) {
            int k0 = (c + 1) * 16;
            cpa16(s2u(&As[nxt][arow * ASTR + aq]), asrc0 + k0);
            cpa16(s2u(&As[nxt][(arow + 64) * ASTR + aq]), asrc1 + k0);
            cpa16(s2u(&Bs[nxt][bk * BSTR + bq * 4]), bsrc + (size_t)k0 * N);
            cpa16(s2u(&Bs[nxt][(bk + 8) * BSTR + bq * 4]), bsrc + (size_t)(k0 + 8) * N);
        }
        CP_COMMIT;
        CP_WAIT1;
        __syncthreads();
        const unsigned* Au = (const unsigned*)As[cur];
        const unsigned* Bu = (const unsigned*)Bs[cur];
#pragma unroll
        for (int ks = 0; ks < 2; ++ks) {
            unsigned a[2][4];
#pragma unroll
            for (int mt = 0; mt < 2; ++mt) {
                int mr = wm * 32 + mt * 16;
                a[mt][0] = Au[(mr + gID    ) * ASTR + ks * 8 + tig];
                a[mt][1] = Au[(mr + gID + 8) * ASTR + ks * 8 + tig];
                a[mt][2] = Au[(mr + gID    ) * ASTR + ks * 8 + tig + 4];
                a[mt][3] = Au[(mr + gID + 8) * ASTR + ks * 8 + tig + 4];
            }
#pragma unroll
            for (int nt = 0; nt < 8; ++nt) {
                int nc = wn * 64 + nt * 8 + gID;
                unsigned b0 = Bu[(ks * 8 + tig    ) * BSTR + nc];
                unsigned b1 = Bu[(ks * 8 + tig + 4) * BSTR + nc];
#pragma unroll
                for (int mt = 0; mt < 2; ++mt)
                    mma_tf32(acc[mt][nt][0], acc[mt][nt][1], acc[mt][nt][2], acc[mt][nt][3],
                             a[mt][0], a[mt][1], a[mt][2], a[mt][3], b0, b1);
            }
        }
        __syncthreads();
    }
#pragma unroll
    for (int mt = 0; mt < 2; ++mt) {
#pragma unroll
        for (int er = 0; er < 2; ++er) {
            int gm = by * 128 + wm * 32 + mt * 16 + gID + er * 8;
            float* crow = g_xw0 + (size_t)gm * N;
#pragma unroll
            for (int nt = 0; nt < 8; ++nt) {
                int gn = bx * 128 + wn * 64 + nt * 8 + tig * 2;
                float2 v = {acc[mt][nt][er * 2 + 0] + bias[gn],
                            acc[mt][nt][er * 2 + 1] + bias[gn + 1]};
                *(float2*)(crow + gn) = v;
            }
        }
    }
}

__global__ void k_logits_tf32(const float* __restrict__ Bm,
                              const float* __restrict__ bias,
                              const int* __restrict__ labels) {
    const int N = Vq, K = Hq;
    __shared__ float As[2][128 * ASTR];
    __shared__ float Bs[2][16 * BSTR];
    __shared__ float pm[128][9];
    __shared__ float ps[128][9];
    const int tid = threadIdx.x;
    const int bx = blockIdx.x, by = blockIdx.y;
    const int warp = tid >> 5, lane = tid & 31;
    const int wm = warp & 3, wn = warp >> 2;
    const int gID = lane >> 2, tig = lane & 3;

    const int arow = tid >> 2;
    const int aq   = (tid & 3) * 4;
    const float* asrc0 = g_out + (size_t)(by * 128 + arow) * K + aq;
    const float* asrc1 = asrc0 + (size_t)64 * K;
    const int bk = tid >> 5, bq = tid & 31;
    const int gnq = bx * 128 + bq * 4;
    const bool bpred = (gnq + 3 < N);
    const float* bsrc = Bm + (size_t)bk * N + (bpred ? gnq : 0);

    float acc[2][8][4];
#pragma unroll
    for (int mt = 0; mt < 2; ++mt)
#pragma unroll
        for (int nt = 0; nt < 8; ++nt)
#pragma unroll
            for (int e = 0; e < 4; ++e) acc[mt][nt][e] = 0.f;

    const int NC = K / 16;
    {
        cpa16(s2u(&As[0][arow * ASTR + aq]), asrc0);
        cpa16(s2u(&As[0][(arow + 64) * ASTR + aq]), asrc1);
        cpa16p(s2u(&Bs[0][bk * BSTR + bq * 4]), bsrc, bpred);
        cpa16p(s2u(&Bs[0][(bk + 8) * BSTR + bq * 4]), bsrc + (size_t)8 * N, bpred);
    }
    CP_COMMIT;
    for (int c = 0; c < NC; ++c) {
        const int cur = c & 1, nxt = cur ^ 1;
        if (c + 1 < NC) {
            int k0 = (c + 1) * 16;
            cpa16(s2u(&As[nxt][arow * ASTR + aq]), asrc0 + k0);
            cpa16(s2u(&As[nxt][(arow + 64) * ASTR + aq]), asrc1 + k0);
            cpa16p(s2u(&Bs[nxt][bk * BSTR + bq * 4]), bsrc + (size_t)k0 * N, bpred);
            cpa16p(s2u(&Bs[nxt][(bk + 8) * BSTR + bq * 4]), bsrc + (size_t)(k0 + 8) * N, bpred);
        }
        CP_COMMIT;
        CP_WAIT1;
        __syncthreads();
        const unsigned* Au = (const unsigned*)As[cur];
        const unsigned* Bu = (const unsigned*)Bs[cur];
#pragma unroll
        for (int ks = 0; ks < 2; ++ks) {
            unsigned a[2][4];
#pragma unroll
            for (int mt = 0; mt < 2; ++mt) {
                int mr = wm * 32 + mt * 16;
                a[mt][0] = Au[(mr + gID    ) * ASTR + ks * 8 + tig];
                a[mt][1] = Au[(mr + gID + 8) * ASTR + ks * 8 + tig];
                a[mt][2] = Au[(mr + gID    ) * ASTR + ks * 8 + tig + 4];
                a[mt][3] = Au[(mr + gID + 8) * ASTR + ks * 8 + tig + 4];
            }
#pragma unroll
            for (int nt = 0; nt < 8; ++nt) {
                int nc = wn * 64 + nt * 8 + gID;
                unsigned b0 = Bu[(ks * 8 + tig    ) * BSTR + nc];
                unsigned b1 = Bu[(ks * 8 + tig + 4) * BSTR + nc];
#pragma unroll
                for (int mt = 0; mt < 2; ++mt)
                    mma_tf32(acc[mt][nt][0], acc[mt][nt][1], acc[mt][nt][2], acc[mt][nt][3],
                             a[mt][0], a[mt][1], a[mt][2], a[mt][3], b0, b1);
            }
        }
        __syncthreads();
    }

#pragma unroll
    for (int mt = 0; mt < 2; ++mt) {
#pragma unroll
        for (int er = 0; er < 2; ++er) {
            int lr = wm * 32 + mt * 16 + gID + er * 8;
            int gm = by * 128 + lr;
            int lab = labels[gm];
            float lm = -1e30f, lsum = 0.f;
            float v[16];
#pragma unroll
            for (int nt = 0; nt < 8; ++nt) {
#pragma unroll
                for (int e = 0; e < 2; ++e) {
                    int gn = bx * 128 + wn * 64 + nt * 8 + tig * 2 + e;
                    float cc = acc[mt][nt][er * 2 + e];
                    if (gn < N) {
                        float z = cc + bias[gn];
                        v[nt * 2 + e] = z;
                        if (gn == lab) g_zl[gm] = z;
                        lm = fmaxf(lm, z);
                    } else v[nt * 2 + e] = -1e30f;
                }
            }
#pragma unroll
            for (int q = 0; q < 16; ++q) lsum += expf(v[q] - lm);
            if (lm <= -1e30f) lsum = 0.f;
            pm[lr][wn * 4 + tig] = lm;
            ps[lr][wn * 4 + tig] = lsum;
        }
    }
    __syncthreads();
    if (tid < 128) {
        float m = -1e30f, s = 0.f;
#pragma unroll
        for (int x = 0; x < 8; ++x) {
            float m2 = pm[tid][x], s2 = ps[tid][x];
            float M = fmaxf(m, m2);
            s = s * expf(m - M) + s2 * expf(m2 - M);
            m = M;
        }
        int gm = by * 128 + tid;
        g_pm[(size_t)gm * NBLK + bx] = m;
        g_ps[(size_t)gm * NBLK + bx] = s;
    }
}

// =======================================================================
// tf32 tensor-core LSTM steps.
// Grid 128 blocks: block = all 128 rows x 16 gate-cols (j0=bx*4; col c:
// g=c>>2, j=j0+(c&3)).  8 warps, warp wm = rows wm*16..+15 (m16 x n16).
// K pipelined by 16 (2-stage cp.async).  SMEM: A [128][20], B [16][24].
// =======================================================================
#define SA  20
#define SB  24

struct StepPre {       // per-thread epilogue prefetch (2 cells per lane)
    float ga[2][4];    // step0: xw0 gates;  step1: b1 gates
    float cold[2], hold[2];
    int   sl[2], b_[2], j_[2];
};

__device__ __forceinline__ void step_mma_loop(
        const float* __restrict__ A0, const float* __restrict__ A1,
        const float* __restrict__ W0, const float* __restrict__ W1,
        int nphase, int j0, float* Asm0, float* Asm1, float* Bsm0, float* Bsm1,
        int tid, int wm, int gID, int tig, float acc[2][4]) {
    const int ar = tid >> 1, aq = (tid & 1) * 8;
    const int bk = tid >> 2, bg = tid & 3;          // tid<64 fills B
    const int NC = nphase * 32;                     // chunks of 16 over K
    float* Asm[2] = {Asm0, Asm1};
    float* Bsm[2] = {Bsm0, Bsm1};

    // stage 0
    {
        const float* Ap = A0;
        cpa16(s2u(&Asm[0][ar * SA + aq]),     Ap + (size_t)ar * Hq + aq);
        cpa16(s2u(&Asm[0][ar * SA + aq + 4]), Ap + (size_t)ar * Hq + aq + 4);
        if (tid < 64)
            cpa16(s2u(&Bsm[0][bk * SB + bg * 4]),
                  W0 + (size_t)bk * Gq + bg * Hq + j0);
    }
    CP_COMMIT;
    for (int c = 0; c < NC; ++c) {
        const int cur = c & 1, nxt = cur ^ 1;
        if (c + 1 < NC) {
            int cc = c + 1;
            const float* Ap = (cc < 32) ? A0 : A1;
            const float* Wp = (cc < 32) ? W0 : W1;
            int k0 = (cc & 31) * 16;
            cpa16(s2u(&Asm[nxt][ar * SA + aq]),     Ap + (size_t)ar * Hq + k0 + aq);
            cpa16(s2u(&Asm[nxt][ar * SA + aq + 4]), Ap + (size_t)ar * Hq + k0 + aq + 4);
            if (tid < 64)
                cpa16(s2u(&Bsm[nxt][bk * SB + bg * 4]),
                      Wp + (size_t)(k0 + bk) * Gq + bg * Hq + j0);
        }
        CP_COMMIT;
        CP_WAIT1;
        __syncthreads();
        const unsigned* Au = (const unsigned*)Asm[cur];
        const unsigned* Bu = (const unsigned*)Bsm[cur];
#pragma unroll
        for (int ks = 0; ks < 2; ++ks) {
            unsigned a0 = Au[(wm * 16 + gID    ) * SA + ks * 8 + tig];
            unsigned a1 = Au[(wm * 16 + gID + 8) * SA + ks * 8 + tig];
            unsigned a2 = Au[(wm * 16 + gID    ) * SA + ks * 8 + tig + 4];
            unsigned a3 = Au[(wm * 16 + gID + 8) * SA + ks * 8 + tig + 4];
#pragma unroll
            for (int nt = 0; nt < 2; ++nt) {
                int n = nt * 8 + gID;
                unsigned b0 = Bu[(ks * 8 + tig    ) * SB + n];
                unsigned b1 = Bu[(ks * 8 + tig + 4) * SB + n];
                mma_tf32(acc[nt][0], acc[nt][1], acc[nt][2], acc[nt][3],
                         a0, a1, a2, a3, b0, b1);
            }
        }
        __syncthreads();
    }
}

// stage warp accs -> smem [16 rows][17] per warp; lane gathers 4 gates/cell
__device__ __forceinline__ void stage_accs(float* stg, int wm, int gID, int tig,
                                           float acc[2][4]) {
#pragma unroll
    for (int nt = 0; nt < 2; ++nt)
#pragma unroll
        for (int er = 0; er < 2; ++er)
#pragma unroll
            for (int e = 0; e < 2; ++e)
                stg[(wm * 16 + gID + er * 8) * 17 + nt * 8 + tig * 2 + e] =
                    acc[nt][er * 2 + e];
}

__global__ void __launch_bounds__(256) lstm_step0_mma(
        const int* __restrict__ seq_len, const float* __restrict__ W0h, int t) {
    __shared__ float Asm[2][128 * SA];
    __shared__ float Bsm[2][16 * SB];
    const int tid = threadIdx.x, lane = tid & 31, wm = tid >> 5;
    const int gID = lane >> 2, tig = lane & 3;
    const int j0 = blockIdx.x * 4;
    const int rb = t & 1, wb = rb ^ 1;
    const float* __restrict__ hbuf = g_h0[rb];

    // epilogue prefetch: cells lane, lane+32 (row = c&15, jl = c>>4)
    StepPre P;
#pragma unroll
    for (int i = 0; i < 2; ++i) {
        int cc = lane + i * 32;
        int b_ = wm * 16 + (cc & 15);
        int j  = j0 + (cc >> 4);
        P.b_[i] = b_; P.j_[i] = j;
        size_t base = ((size_t)b_ * Tq + t) * Gq;
#pragma unroll
        for (int g = 0; g < 4; ++g) P.ga[i][g] = __ldg(&g_xw0[base + g * Hq + j]);
        P.cold[i] = g_c0[b_ * Hq + j];
        P.hold[i] = hbuf[b_ * Hq + j];
        P.sl[i]   = __ldg(&seq_len[b_]);
    }

    float acc[2][4] = {};
    step_mma_loop(hbuf, hbuf, W0h, W0h, 1, j0,
                  Asm[0], Asm[1], Bsm[0], Bsm[1], tid, wm, gID, tig, acc);

    __syncthreads();
    float* stg = Asm[0];
    stage_accs(stg, wm, gID, tig, acc);
    __syncwarp();
#pragma unroll
    for (int i = 0; i < 2; ++i) {
        int cc = lane + i * 32;
        int row = wm * 16 + (cc & 15), jl = cc >> 4;
        float gi = stg[row * 17 + 0 + jl] + P.ga[i][0];
        float gc_= stg[row * 17 + 4 + jl] + P.ga[i][1];
        float gf = stg[row * 17 + 8 + jl] + P.ga[i][2];
        float go = stg[row * 17 + 12 + jl] + P.ga[i][3];
        bool m = t < P.sl[i];
        int s = P.b_[i] * Hq + P.j_[i];
        float cn = sigf(gf) * P.cold[i] + sigf(gi) * tanhf(gc_);
        float hn = sigf(go) * tanhf(cn);
        g_c0[s]     = m ? cn : P.cold[i];
        g_h0[wb][s] = m ? hn : P.hold[i];
        g_o0[s]     = m ? hn : 0.f;
    }
}

__global__ void __launch_bounds__(256) lstm_step1_mma(
        const int* __restrict__ seq_len,
        const float* __restrict__ W1x, const float* __restrict__ W1h,
        const float* __restrict__ b1, int t) {
    __shared__ float Asm[2][128 * SA];
    __shared__ float Bsm[2][16 * SB];
    const int tid = threadIdx.x, lane = tid & 31, wm = tid >> 5;
    const int gID = lane >> 2, tig = lane & 3;
    const int j0 = blockIdx.x * 4;
    const int rb = t & 1, wb = rb ^ 1;
    const float* __restrict__ h1buf = g_h1[rb];

    StepPre P;
#pragma unroll
    for (int i = 0; i < 2; ++i) {
        int cc = lane + i * 32;
        int b_ = wm * 16 + (cc & 15);
        int j  = j0 + (cc >> 4);
        P.b_[i] = b_; P.j_[i] = j;
#pragma unroll
        for (int g = 0; g < 4; ++g) P.ga[i][g] = __ldg(&b1[g * Hq + j]);
        P.cold[i] = g_c1[b_ * Hq + j];
        P.hold[i] = h1buf[b_ * Hq + j];
        P.sl[i]   = __ldg(&seq_len[b_]);
    }

    float acc[2][4] = {};
    step_mma_loop(g_o0, h1buf, W1x, W1h, 2, j0,
                  Asm[0], Asm[1], Bsm[0], Bsm[1], tid, wm, gID, tig, acc);

    __syncthreads();
    float* stg = Asm[0];
    stage_accs(stg, wm, gID, tig, acc);
    __syncwarp();
#pragma unroll
    for (int i = 0; i < 2; ++i) {
        int cc = lane + i * 32;
        int row = wm * 16 + (cc & 15), jl = cc >> 4;
        float gi = stg[row * 17 + 0 + jl] + P.ga[i][0];
        float gc_= stg[row * 17 + 4 + jl] + P.ga[i][1];
        float gf = stg[row * 17 + 8 + jl] + P.ga[i][2];
        float go = stg[row * 17 + 12 + jl] + P.ga[i][3];
        bool m = t < P.sl[i];
        int s = P.b_[i] * Hq + P.j_[i];
        float cn = sigf(gf) * P.cold[i] + sigf(gi) * tanhf(gc_);
        float hn = sigf(go) * tanhf(cn);
        g_c1[s]     = m ? cn : P.cold[i];
        g_h1[wb][s] = m ? hn : P.hold[i];
        g_out[((size_t)P.b_[i] * Tq + t) * Hq + P.j_[i]] = m ? hn : 0.f;
    }
}

// ---------------- partial softmax merge; xent ----------------
__global__ void k_xent_reduce() {
    const int row  = blockIdx.x * 8 + (threadIdx.x >> 5);
    const int lane = threadIdx.x & 31;
    float m = -1e30f, s = 0.f;
    for (int p = lane; p < NBLK; p += 32) {
        float m2 = g_pm[(size_t)row * NBLK + p];
        float s2 = g_ps[(size_t)row * NBLK + p];
        float M = fmaxf(m, m2);
        s = s * expf(m - M) + s2 * expf(m2 - M);
        m = M;
    }
#pragma unroll
    for (int o = 16; o > 0; o >>= 1) {
        float m2 = __shfl_xor_sync(0xffffffff, m, o);
        float s2 = __shfl_xor_sync(0xffffffff, s, o);
        float M = fmaxf(m, m2);
        s = s * expf(m - M) + s2 * expf(m2 - M);
        m = M;
    }
    if (lane == 0) g_xent[row] = -(g_zl[row] - m - logf(s));
}

// ---------------- final masked reduction ----------------
__global__ void k_loss(const float* __restrict__ seq_mask, float* __restrict__ out) {
    const int t = threadIdx.x;
    float sx = 0.f, sw_ = 0.f;
    for (int b = 0; b < Bq; ++b) {
        int i = b * Tq + t;
        float w = seq_mask[i];
        sx  += g_xent[i] * w;
        sw_ += w;
    }
    __shared__ float sh[64];
    sh[t] = sx / (sw_ + 1e-12f);
    __syncthreads();
    for (int o = 32; o > 0; o >>= 1) { if (t < o) sh[t] += sh[t + o]; __syncthreads(); }
    if (t == 0) out[0] = sh[0] / Tq;
}

// ---------------- launch ----------------
extern "C" void kernel_launch(void* const* d_in, const int* in_sizes, int n_in,
                              void* d_out, int out_size) {
    const int*   features = (const int*)  d_in[0];
    const int*   labels   = (const int*)  d_in[1];
    const int*   seq_len  = (const int*)  d_in[2];
    const float* seq_mask = (const float*)d_in[3];
    const float* emb      = (const float*)d_in[4];
    const float* W0x      = (const float*)d_in[5];
    const float* W0h      = (const float*)d_in[6];
    const float* b0       = (const float*)d_in[7];
    const float* W1x      = (const float*)d_in[8];
    const float* W1h      = (const float*)d_in[9];
    const float* b1       = (const float*)d_in[10];
    const float* smw      = (const float*)d_in[11];
    const float* smb      = (const float*)d_in[12];
    float* out = (float*)d_out;

    k_init<<<(Bq * Hq + 255) / 256, 256>>>();

    k_xw0_tf32<<<dim3(Gq / 128, BTq / 128), 256>>>(emb, features, W0x, b0);

    for (int t = 0; t < Tq; ++t) {
        lstm_step0_mma<<<128, 256>>>(seq_len, W0h, t);
        lstm_step1_mma<<<128, 256>>>(seq_len, W1x, W1h, b1, t);
    }

    k_logits_tf32<<<dim3(NBLK, BTq / 128), 256>>>(smw, smb, labels);
    k_xent_reduce<<<BTq / 8, 256>>>();
    k_loss<<<1, 64>>>(seq_mask, out);
}

// round 8
// speedup vs baseline: 4.4766x; 1.1547x over previous
#include <cuda_runtime.h>
#include <cuda_bf16.h>
#include <cstddef>
#include <cstdint>

#define Bq   128
#define Tq   64
#define Hq   512
#define Vq   10000
#define Gq   2048            // 4*H
#define BTq  (Bq*Tq)         // 8192
#define NBLK 79              // ceil(V/128)

// ---------------- scratch ----------------
__device__ float g_xw0[(size_t)BTq * Gq];
__device__ float g_out[(size_t)BTq * Hq];
__device__ float g_pm[(size_t)BTq * NBLK];
__device__ float g_ps[(size_t)BTq * NBLK];
__device__ float g_zl[BTq];
__device__ float g_xent[BTq];
__device__ float g_h0[2][Bq * Hq];
__device__ float g_h1[2][Bq * Hq];
__device__ float g_c0[Bq * Hq];
__device__ float g_c1[Bq * Hq];
__device__ float g_o0[Bq * Hq];

__device__ __forceinline__ float sigf(float x) { return 1.f / (1.f + expf(-x)); }

__device__ __forceinline__ uint32_t s2u(const void* p) {
    return (uint32_t)__cvta_generic_to_shared(p);
}
__device__ __forceinline__ void cpa16(uint32_t dst, const void* src) {
    asm volatile("cp.async.cg.shared.global [%0], [%1], 16;" :: "r"(dst), "l"(src));
}
__device__ __forceinline__ void cpa16p(uint32_t dst, const void* src, bool pred) {
    int sz = pred ? 16 : 0;
    asm volatile("cp.async.cg.shared.global [%0], [%1], 16, %2;" :: "r"(dst), "l"(src), "r"(sz));
}
#define CP_COMMIT asm volatile("cp.async.commit_group;")
#define CP_WAIT1  asm volatile("cp.async.wait_group 1;")
#define CP_WAIT3  asm volatile("cp.async.wait_group 3;")

__device__ __forceinline__ void mma_tf32(float& d0, float& d1, float& d2, float& d3,
                                         unsigned a0, unsigned a1, unsigned a2, unsigned a3,
                                         unsigned b0, unsigned b1) {
    asm volatile(
        "mma.sync.aligned.m16n8k8.row.col.f32.tf32.tf32.f32 "
        "{%0,%1,%2,%3}, {%4,%5,%6,%7}, {%8,%9}, {%0,%1,%2,%3};"
        : "+f"(d0), "+f"(d1), "+f"(d2), "+f"(d3)
        : "r"(a0), "r"(a1), "r"(a2), "r"(a3), "r"(b0), "r"(b1));
}

// ---------------- init ----------------
__global__ void k_init() {
    int i = blockIdx.x * blockDim.x + threadIdx.x;
    if (i < Bq * Hq) {
        g_h0[0][i] = 0.f; g_c0[i] = 0.f;
        g_h1[0][i] = 0.f; g_c1[i] = 0.f;
    }
}

// =======================================================================
// big tf32 GEMMs: block 128x128, warp 32x64, k-chunk 16, 2-stage cp.async
// =======================================================================
#define ASTR 20
#define BSTR 136

__global__ void k_xw0_tf32(const float* __restrict__ emb, const int* __restrict__ feat,
                           const float* __restrict__ Bm, const float* __restrict__ bias) {
    const int N = Gq, K = Hq;
    __shared__ float As[2][128 * ASTR];
    __shared__ float Bs[2][16 * BSTR];
    const int tid = threadIdx.x;
    const int bx = blockIdx.x, by = blockIdx.y;
    const int warp = tid >> 5, lane = tid & 31;
    const int wm = warp & 3, wn = warp >> 2;
    const int gID = lane >> 2, tig = lane & 3;

    const int arow = tid >> 2;
    const int aq   = (tid & 3) * 4;
    const float* asrc0 = emb + (size_t)feat[by * 128 + arow] * K + aq;
    const float* asrc1 = emb + (size_t)feat[by * 128 + arow + 64] * K + aq;
    const int bk = tid >> 5, bq = tid & 31;
    const float* bsrc = Bm + (size_t)bk * N + bx * 128 + bq * 4;

    float acc[2][8][4];
#pragma unroll
    for (int mt = 0; mt < 2; ++mt)
#pragma unroll
        for (int nt = 0; nt < 8; ++nt)
#pragma unroll
            for (int e = 0; e < 4; ++e) acc[mt][nt][e] = 0.f;

    const int NC = K / 16;
    {
        cpa16(s2u(&As[0][arow * ASTR + aq]), asrc0);
        cpa16(s2u(&As[0][(arow + 64) * ASTR + aq]), asrc1);
        cpa16(s2u(&Bs[0][bk * BSTR + bq * 4]), bsrc);
        cpa16(s2u(&Bs[0][(bk + 8) * BSTR + bq * 4]), bsrc + (size_t)8 * N);
    }
    CP_COMMIT;
    for (int c = 0; c < NC; ++c) {
        const int cur = c & 1, nxt = cur ^ 1;
        if (c + 1 < NC) {
            int k0 = (c + 1) * 16;
            cpa16(s2u(&As[nxt][arow * ASTR + aq]), asrc0 + k0);
            cpa16(s2u(&As[nxt][(arow + 64) * ASTR + aq]), asrc1 + k0);
            cpa16(s2u(&Bs[nxt][bk * BSTR + bq * 4]), bsrc + (size_t)k0 * N);
            cpa16(s2u(&Bs[nxt][(bk + 8) * BSTR + bq * 4]), bsrc + (size_t)(k0 + 8) * N);
        }
        CP_COMMIT;
        CP_WAIT1;
        __syncthreads();
        const unsigned* Au = (const unsigned*)As[cur];
        const unsigned* Bu = (const unsigned*)Bs[cur];
#pragma unroll
        for (int ks = 0; ks < 2; ++ks) {
            unsigned a[2][4];
#pragma unroll
            for (int mt = 0; mt < 2; ++mt) {
                int mr = wm * 32 + mt * 16;
                a[mt][0] = Au[(mr + gID    ) * ASTR + ks * 8 + tig];
                a[mt][1] = Au[(mr + gID + 8) * ASTR + ks * 8 + tig];
                a[mt][2] = Au[(mr + gID    ) * ASTR + ks * 8 + tig + 4];
                a[mt][3] = Au[(mr + gID + 8) * ASTR + ks * 8 + tig + 4];
            }
#pragma unroll
            for (int nt = 0; nt < 8; ++nt) {
                int nc = wn * 64 + nt * 8 + gID;
                unsigned b0 = Bu[(ks * 8 + tig    ) * BSTR + nc];
                unsigned b1 = Bu[(ks * 8 + tig + 4) * BSTR + nc];
#pragma unroll
                for (int mt = 0; mt < 2; ++mt)
                    mma_tf32(acc[mt][nt][0], acc[mt][nt][1], acc[mt][nt][2], acc[mt][nt][3],
                             a[mt][0], a[mt][1], a[mt][2], a[mt][3], b0, b1);
            }
        }
        __syncthreads();
    }
#pragma unroll
    for (int mt = 0; mt < 2; ++mt) {
#pragma unroll
        for (int er = 0; er < 2; ++er) {
            int gm = by * 128 + wm * 32 + mt * 16 + gID + er * 8;
            float* crow = g_xw0 + (size_t)gm * N;
#pragma unroll
            for (int nt = 0; nt < 8; ++nt) {
                int gn = bx * 128 + wn * 64 + nt * 8 + tig * 2;
                float2 v = {acc[mt][nt][er * 2 + 0] + bias[gn],
                            acc[mt][nt][er * 2 + 1] + bias[gn + 1]};
                *(float2*)(crow + gn) = v;
            }
        }
    }
}

__global__ void k_logits_tf32(const float* __restrict__ Bm,
                              const float* __restrict__ bias,
                              const int* __restrict__ labels) {
    const int N = Vq, K = Hq;
    __shared__ float As[2][128 * ASTR];
    __shared__ float Bs[2][16 * BSTR];
    __shared__ float pm[128][9];
    __shared__ float ps[128][9];
    const int tid = threadIdx.x;
    const int bx = blockIdx.x, by = blockIdx.y;
    const int warp = tid >> 5, lane = tid & 31;
    const int wm = warp & 3, wn = warp >> 2;
    const int gID = lane >> 2, tig = lane & 3;

    const int arow = tid >> 2;
    const int aq   = (tid & 3) * 4;
    const float* asrc0 = g_out + (size_t)(by * 128 + arow) * K + aq;
    const float* asrc1 = asrc0 + (size_t)64 * K;
    const int bk = tid >> 5, bq = tid & 31;
    const int gnq = bx * 128 + bq * 4;
    const bool bpred = (gnq + 3 < N);
    const float* bsrc = Bm + (size_t)bk * N + (bpred ? gnq : 0);

    float acc[2][8][4];
#pragma unroll
    for (int mt = 0; mt < 2; ++mt)
#pragma unroll
        for (int nt = 0; nt < 8; ++nt)
#pragma unroll
            for (int e = 0; e < 4; ++e) acc[mt][nt][e] = 0.f;

    const int NC = K / 16;
    {
        cpa16(s2u(&As[0][arow * ASTR + aq]), asrc0);
        cpa16(s2u(&As[0][(arow + 64) * ASTR + aq]), asrc1);
        cpa16p(s2u(&Bs[0][bk * BSTR + bq * 4]), bsrc, bpred);
        cpa16p(s2u(&Bs[0][(bk + 8) * BSTR + bq * 4]), bsrc + (size_t)8 * N, bpred);
    }
    CP_COMMIT;
    for (int c = 0; c < NC; ++c) {
        const int cur = c & 1, nxt = cur ^ 1;
        if (c + 1 < NC) {
            int k0 = (c + 1) * 16;
            cpa16(s2u(&As[nxt][arow * ASTR + aq]), asrc0 + k0);
            cpa16(s2u(&As[nxt][(arow + 64) * ASTR + aq]), asrc1 + k0);
            cpa16p(s2u(&Bs[nxt][bk * BSTR + bq * 4]), bsrc + (size_t)k0 * N, bpred);
            cpa16p(s2u(&Bs[nxt][(bk + 8) * BSTR + bq * 4]), bsrc + (size_t)(k0 + 8) * N, bpred);
        }
        CP_COMMIT;
        CP_WAIT1;
        __syncthreads();
        const unsigned* Au = (const unsigned*)As[cur];
        const unsigned* Bu = (const unsigned*)Bs[cur];
#pragma unroll
        for (int ks = 0; ks < 2; ++ks) {
            unsigned a[2][4];
#pragma unroll
            for (int mt = 0; mt < 2; ++mt) {
                int mr = wm * 32 + mt * 16;
                a[mt][0] = Au[(mr + gID    ) * ASTR + ks * 8 + tig];
                a[mt][1] = Au[(mr + gID + 8) * ASTR + ks * 8 + tig];
                a[mt][2] = Au[(mr + gID    ) * ASTR + ks * 8 + tig + 4];
                a[mt][3] = Au[(mr + gID + 8) * ASTR + ks * 8 + tig + 4];
            }
#pragma unroll
            for (int nt = 0; nt < 8; ++nt) {
                int nc = wn * 64 + nt * 8 + gID;
                unsigned b0 = Bu[(ks * 8 + tig    ) * BSTR + nc];
                unsigned b1 = Bu[(ks * 8 + tig + 4) * BSTR + nc];
#pragma unroll
                for (int mt = 0; mt < 2; ++mt)
                    mma_tf32(acc[mt][nt][0], acc[mt][nt][1], acc[mt][nt][2], acc[mt][nt][3],
                             a[mt][0], a[mt][1], a[mt][2], a[mt][3], b0, b1);
            }
        }
        __syncthreads();
    }

#pragma unroll
    for (int mt = 0; mt < 2; ++mt) {
#pragma unroll
        for (int er = 0; er < 2; ++er) {
            int lr = wm * 32 + mt * 16 + gID + er * 8;
            int gm = by * 128 + lr;
            int lab = labels[gm];
            float lm = -1e30f, lsum = 0.f;
            float v[16];
#pragma unroll
            for (int nt = 0; nt < 8; ++nt) {
#pragma unroll
                for (int e = 0; e < 2; ++e) {
                    int gn = bx * 128 + wn * 64 + nt * 8 + tig * 2 + e;
                    float cc = acc[mt][nt][er * 2 + e];
                    if (gn < N) {
                        float z = cc + bias[gn];
                        v[nt * 2 + e] = z;
                        if (gn == lab) g_zl[gm] = z;
                        lm = fmaxf(lm, z);
                    } else v[nt * 2 + e] = -1e30f;
                }
            }
#pragma unroll
            for (int q = 0; q < 16; ++q) lsum += expf(v[q] - lm);
            if (lm <= -1e30f) lsum = 0.f;
            pm[lr][wn * 4 + tig] = lm;
            ps[lr][wn * 4 + tig] = lsum;
        }
    }
    __syncthreads();
    if (tid < 128) {
        float m = -1e30f, s = 0.f;
#pragma unroll
        for (int x = 0; x < 8; ++x) {
            float m2 = pm[tid][x], s2 = ps[tid][x];
            float M = fmaxf(m, m2);
            s = s * expf(m - M) + s2 * expf(m2 - M);
            m = M;
        }
        int gm = by * 128 + tid;
        g_pm[(size_t)gm * NBLK + bx] = m;
        g_ps[(size_t)gm * NBLK + bx] = s;
    }
}

// =======================================================================
// tf32 tensor-core LSTM steps — 4-stage cp.async pipeline (prefetch dist 3).
// Grid 128 blocks: block = 128 rows x 16 gate-cols (4 j x 4 g); 8 warps,
// warp wm = rows wm*16..+15 (m16 x n16).  SMEM: 4 x (A[128][20], B[16][24]).
// =======================================================================
#define SA  20
#define SB  24
#define NSTG 4

struct StepPre {
    float ga[2][4];
    float cold[2], hold[2];
    int   sl[2], b_[2], j_[2];
};

__device__ __forceinline__ void step_mma_loop(
        const float* __restrict__ A0, const float* __restrict__ A1,
        const float* __restrict__ W0, const float* __restrict__ W1,
        int nphase, int j0, float* AsmBase, float* BsmBase,
        int tid, int wm, int gID, int tig, float acc[2][4]) {
    const int ar = tid >> 1, aq = (tid & 1) * 8;
    const int bk = tid >> 2, bg = tid & 3;          // tid<64 fills B
    const int NC = nphase * 32;

    auto issue = [&](int cc) {
        const float* Ap = (cc < 32) ? A0 : A1;
        const float* Wp = (cc < 32) ? W0 : W1;
        int k0 = (cc & 31) * 16;
        float* Ab = AsmBase + (cc & (NSTG - 1)) * (128 * SA);
        float* Bb = BsmBase + (cc & (NSTG - 1)) * (16 * SB);
        cpa16(s2u(&Ab[ar * SA + aq]),     Ap + (size_t)ar * Hq + k0 + aq);
        cpa16(s2u(&Ab[ar * SA + aq + 4]), Ap + (size_t)ar * Hq + k0 + aq + 4);
        if (tid < 64)
            cpa16(s2u(&Bb[bk * SB + bg * 4]),
                  Wp + (size_t)(k0 + bk) * Gq + bg * Hq + j0);
    };

    // prologue: stages 0..2
#pragma unroll
    for (int s = 0; s < NSTG - 1; ++s) { issue(s); CP_COMMIT; }

    for (int c = 0; c < NC; ++c) {
        if (c + NSTG - 1 < NC) issue(c + NSTG - 1);
        CP_COMMIT;                 // unconditional: keeps group index == chunk index
        CP_WAIT3;                  // chunk c retired
        __syncthreads();
        const unsigned* Au = (const unsigned*)(AsmBase + (c & (NSTG - 1)) * (128 * SA));
        const unsigned* Bu = (const unsigned*)(BsmBase + (c & (NSTG - 1)) * (16 * SB));
#pragma unroll
        for (int ks = 0; ks < 2; ++ks) {
            unsigned a0 = Au[(wm * 16 + gID    ) * SA + ks * 8 + tig];
            unsigned a1 = Au[(wm * 16 + gID + 8) * SA + ks * 8 + tig];
            unsigned a2 = Au[(wm * 16 + gID    ) * SA + ks * 8 + tig + 4];
            unsigned a3 = Au[(wm * 16 + gID + 8) * SA + ks * 8 + tig + 4];
#pragma unroll
            for (int nt = 0; nt < 2; ++nt) {
                int n = nt * 8 + gID;
                unsigned b0 = Bu[(ks * 8 + tig    ) * SB + n];
                unsigned b1 = Bu[(ks * 8 + tig + 4) * SB + n];
                mma_tf32(acc[nt][0], acc[nt][1], acc[nt][2], acc[nt][3],
                         a0, a1, a2, a3, b0, b1);
            }
        }
        __syncthreads();
    }
}

__device__ __forceinline__ void stage_accs(float* stg, int wm, int gID, int tig,
                                           float acc[2][4]) {
#pragma unroll
    for (int nt = 0; nt < 2; ++nt)
#pragma unroll
        for (int er = 0; er < 2; ++er)
#pragma unroll
            for (int e = 0; e < 2; ++e)
                stg[(wm * 16 + gID + er * 8) * 17 + nt * 8 + tig * 2 + e] =
                    acc[nt][er * 2 + e];
}

__global__ void __launch_bounds__(256) lstm_step0_mma(
        const int* __restrict__ seq_len, const float* __restrict__ W0h, int t) {
    __shared__ float Asm[NSTG][128 * SA];
    __shared__ float Bsm[NSTG][16 * SB];
    const int tid = threadIdx.x, lane = tid & 31, wm = tid >> 5;
    const int gID = lane >> 2, tig = lane & 3;
    const int j0 = blockIdx.x * 4;
    const int rb = t & 1, wb = rb ^ 1;
    const float* __restrict__ hbuf = g_h0[rb];

    StepPre P;
#pragma unroll
    for (int i = 0; i < 2; ++i) {
        int cc = lane + i * 32;
        int b_ = wm * 16 + (cc & 15);
        int j  = j0 + (cc >> 4);
        P.b_[i] = b_; P.j_[i] = j;
        size_t base = ((size_t)b_ * Tq + t) * Gq;
#pragma unroll
        for (int g = 0; g < 4; ++g) P.ga[i][g] = __ldg(&g_xw0[base + g * Hq + j]);
        P.cold[i] = g_c0[b_ * Hq + j];
        P.hold[i] = hbuf[b_ * Hq + j];
        P.sl[i]   = __ldg(&seq_len[b_]);
    }

    float acc[2][4] = {};
    step_mma_loop(hbuf, hbuf, W0h, W0h, 1, j0,
                  &Asm[0][0], &Bsm[0][0], tid, wm, gID, tig, acc);

    __syncthreads();
    float* stg = &Asm[0][0];
    stage_accs(stg, wm, gID, tig, acc);
    __syncwarp();
#pragma unroll
    for (int i = 0; i < 2; ++i) {
        int cc = lane + i * 32;
        int row = wm * 16 + (cc & 15), jl = cc >> 4;
        float gi = stg[row * 17 + 0 + jl] + P.ga[i][0];
        float gc_= stg[row * 17 + 4 + jl] + P.ga[i][1];
        float gf = stg[row * 17 + 8 + jl] + P.ga[i][2];
        float go = stg[row * 17 + 12 + jl] + P.ga[i][3];
        bool m = t < P.sl[i];
        int s = P.b_[i] * Hq + P.j_[i];
        float cn = sigf(gf) * P.cold[i] + sigf(gi) * tanhf(gc_);
        float hn = sigf(go) * tanhf(cn);
        g_c0[s]     = m ? cn : P.cold[i];
        g_h0[wb][s] = m ? hn : P.hold[i];
        g_o0[s]     = m ? hn : 0.f;
    }
}

__global__ void __launch_bounds__(256) lstm_step1_mma(
        const int* __restrict__ seq_len,
        const float* __restrict__ W1x, const float* __restrict__ W1h,
        const float* __restrict__ b1, int t) {
    __shared__ float Asm[NSTG][128 * SA];
    __shared__ float Bsm[NSTG][16 * SB];
    const int tid = threadIdx.x, lane = tid & 31, wm = tid >> 5;
    const int gID = lane >> 2, tig = lane & 3;
    const int j0 = blockIdx.x * 4;
    const int rb = t & 1, wb = rb ^ 1;
    const float* __restrict__ h1buf = g_h1[rb];

    StepPre P;
#pragma unroll
    for (int i = 0; i < 2; ++i) {
        int cc = lane + i * 32;
        int b_ = wm * 16 + (cc & 15);
        int j  = j0 + (cc >> 4);
        P.b_[i] = b_; P.j_[i] = j;
#pragma unroll
        for (int g = 0; g < 4; ++g) P.ga[i][g] = __ldg(&b1[g * Hq + j]);
        P.cold[i] = g_c1[b_ * Hq + j];
        P.hold[i] = h1buf[b_ * Hq + j];
        P.sl[i]   = __ldg(&seq_len[b_]);
    }

    float acc[2][4] = {};
    step_mma_loop(g_o0, h1buf, W1x, W1h, 2, j0,
                  &Asm[0][0], &Bsm[0][0], tid, wm, gID, tig, acc);

    __syncthreads();
    float* stg = &Asm[0][0];
    stage_accs(stg, wm, gID, tig, acc);
    __syncwarp();
#pragma unroll
    for (int i = 0; i < 2; ++i) {
        int cc = lane + i * 32;
        int row = wm * 16 + (cc & 15), jl = cc >> 4;
        float gi = stg[row * 17 + 0 + jl] + P.ga[i][0];
        float gc_= stg[row * 17 + 4 + jl] + P.ga[i][1];
        float gf = stg[row * 17 + 8 + jl] + P.ga[i][2];
        float go = stg[row * 17 + 12 + jl] + P.ga[i][3];
        bool m = t < P.sl[i];
        int s = P.b_[i] * Hq + P.j_[i];
        float cn = sigf(gf) * P.cold[i] + sigf(gi) * tanhf(gc_);
        float hn = sigf(go) * tanhf(cn);
        g_c1[s]     = m ? cn : P.cold[i];
        g_h1[wb][s] = m ? hn : P.hold[i];
        g_out[((size_t)P.b_[i] * Tq + t) * Hq + P.j_[i]] = m ? hn : 0.f;
    }
}

// ---------------- partial softmax merge; xent ----------------
__global__ void k_xent_reduce() {
    const int row  = blockIdx.x * 8 + (threadIdx.x >> 5);
    const int lane = threadIdx.x & 31;
    float m = -1e30f, s = 0.f;
    for (int p = lane; p < NBLK; p += 32) {
        float m2 = g_pm[(size_t)row * NBLK + p];
        float s2 = g_ps[(size_t)row * NBLK + p];
        float M = fmaxf(m, m2);
        s = s * expf(m - M) + s2 * expf(m2 - M);
        m = M;
    }
#pragma unroll
    for (int o = 16; o > 0; o >>= 1) {
        float m2 = __shfl_xor_sync(0xffffffff, m, o);
        float s2 = __shfl_xor_sync(0xffffffff, s, o);
        float M = fmaxf(m, m2);
        s = s * expf(m - M) + s2 * expf(m2 - M);
        m = M;
    }
    if (lane == 0) g_xent[row] = -(g_zl[row] - m - logf(s));
}

// ---------------- final masked reduction ----------------
__global__ void k_loss(const float* __restrict__ seq_mask, float* __restrict__ out) {
    const int t = threadIdx.x;
    float sx = 0.f, sw_ = 0.f;
    for (int b = 0; b < Bq; ++b) {
        int i = b * Tq + t;
        float w = seq_mask[i];
        sx  += g_xent[i] * w;
        sw_ += w;
    }
    __shared__ float sh[64];
    sh[t] = sx / (sw_ + 1e-12f);
    __syncthreads();
    for (int o = 32; o > 0; o >>= 1) { if (t < o) sh[t] += sh[t + o]; __syncthreads(); }
    if (t == 0) out[0] = sh[0] / Tq;
}

// ---------------- launch ----------------
extern "C" void kernel_launch(void* const* d_in, const int* in_sizes, int n_in,
                              void* d_out, int out_size) {
    const int*   features = (const int*)  d_in[0];
    const int*   labels   = (const int*)  d_in[1];
    const int*   seq_len  = (const int*)  d_in[2];
    const float* seq_mask = (const float*)d_in[3];
    const float* emb      = (const float*)d_in[4];
    const float* W0x      = (const float*)d_in[5];
    const float* W0h      = (const float*)d_in[6];
    const float* b0       = (const float*)d_in[7];
    const float* W1x      = (const float*)d_in[8];
    const float* W1h      = (const float*)d_in[9];
    const float* b1       = (const float*)d_in[10];
    const float* smw      = (const float*)d_in[11];
    const float* smb      = (const float*)d_in[12];
    float* out = (float*)d_out;

    k_init<<<(Bq * Hq + 255) / 256, 256>>>();

    k_xw0_tf32<<<dim3(Gq / 128, BTq / 128), 256>>>(emb, features, W0x, b0);

    for (int t = 0; t < Tq; ++t) {
        lstm_step0_mma<<<128, 256>>>(seq_len, W0h, t);
        lstm_step1_mma<<<128, 256>>>(seq_len, W1x, W1h, b1, t);
    }

    k_logits_tf32<<<dim3(NBLK, BTq / 128), 256>>>(smw, smb, labels);
    k_xent_reduce<<<BTq / 8, 256>>>();
    k_loss<<<1, 64>>>(seq_mask, out);
}